// round 8
// baseline (speedup 1.0000x reference)
#include <cuda_runtime.h>
#include <stdint.h>

#define B_  4
#define S_  1024
#define D_  1024
#define H_  16
#define HD_ 64
#define M_  (B_ * S_)     // 4096

// ---------------------------------------------------------------------------
// Scratch (device globals)
// ---------------------------------------------------------------------------
__device__ __align__(16) float g_X   [(size_t)M_ * D_];
__device__ __align__(16) float g_Wqkv[(size_t)3 * D_ * D_];
__device__ __align__(16) float g_bqkv[3 * D_];
__device__ __align__(16) float g_W1r [(size_t)2 * D_ * D_];
__device__ __align__(16) float g_W2r [(size_t)2 * D_ * D_];
__device__ __align__(16) float g_QKV [(size_t)M_ * 3 * D_];   // V region unused
__device__ __align__(16) float g_Vt  [(size_t)B_ * H_ * HD_ * S_];  // V^T per head
__device__ __align__(16) float g_C   [(size_t)M_ * D_];
__device__ __align__(16) float g_Hid [(size_t)M_ * 2 * D_];

// ---------------------------------------------------------------------------
__device__ __forceinline__ float to_tf32(float x) {
    uint32_t u;
    asm("cvt.rna.tf32.f32 %0, %1;" : "=r"(u) : "f"(x));
    return __uint_as_float(u);
}

__device__ __forceinline__ void mma_tf32(float* c, const float* a, const float* b) {
    asm volatile(
        "mma.sync.aligned.m16n8k8.row.col.f32.tf32.tf32.f32 "
        "{%0,%1,%2,%3}, {%4,%5,%6,%7}, {%8,%9}, {%0,%1,%2,%3};\n"
        : "+f"(c[0]), "+f"(c[1]), "+f"(c[2]), "+f"(c[3])
        : "r"(__float_as_uint(a[0])), "r"(__float_as_uint(a[1])),
          "r"(__float_as_uint(a[2])), "r"(__float_as_uint(a[3])),
          "r"(__float_as_uint(b[0])), "r"(__float_as_uint(b[1])));
}

__device__ __forceinline__ uint32_t smem_u32(const void* p) {
    uint32_t a;
    asm("{ .reg .u64 t; cvta.to.shared.u64 t, %1; cvt.u32.u64 %0, t; }"
        : "=r"(a) : "l"(p));
    return a;
}

__device__ __forceinline__ void cp_async16(uint32_t dst, const void* src) {
    asm volatile("cp.async.cg.shared.global [%0], [%1], 16;"
                 :: "r"(dst), "l"(src) : "memory");
}

// ---------------------------------------------------------------------------
// Prep: one fused rounding pass over x, Wq, Wk, Wv, W1, W2
// ---------------------------------------------------------------------------
struct RoundSegs {
    const float* src[6];
    float*       dst[6];
    int          cum[7];    // cumulative float4 counts
};

__global__ void round_all(RoundSegs P) {
    const int i = blockIdx.x * blockDim.x + threadIdx.x;
    if (i >= P.cum[6]) return;
#pragma unroll
    for (int j = 0; j < 6; j++) {
        if (i < P.cum[j + 1]) {
            const int k = i - P.cum[j];
            float4 v = ((const float4*)P.src[j])[k];
            v.x = to_tf32(v.x); v.y = to_tf32(v.y);
            v.z = to_tf32(v.z); v.w = to_tf32(v.w);
            ((float4*)P.dst[j])[k] = v;
            return;
        }
    }
}

__global__ void concat_bias(const float* __restrict__ a, const float* __restrict__ b,
                            const float* __restrict__ c, float* __restrict__ dst) {
    const int i = blockIdx.x * blockDim.x + threadIdx.x;
    if (i < 3 * D_)
        dst[i] = (i < D_) ? a[i] : ((i < 2 * D_) ? b[i - D_] : c[i - 2 * D_]);
}

// ---------------------------------------------------------------------------
// GEMM common constants
// ---------------------------------------------------------------------------
#define ASTR 24

// ===== 128x256 tile kernel (QKV + MLP1): 3-stage cp.async, warp tile 64x64 ==
#define W_AFL (128 * ASTR)                 // A floats per stage (3072)
#define W_BFL (256 * ASTR)                 // B floats per stage (6144)
#define W_STGFL (W_AFL + W_BFL)            // 9216 floats = 36,864 B
#define W_NST 3
#define GEMM256_SMEM (W_NST * W_STGFL * 4) // 110,592 B

// QKV_MODE: Q columns (n<1024) pre-scaled by 0.125; V columns (n>=2048)
// redirected to Vt[(b*1024 + d)*1024 + s] instead of C.
template <bool RELU, bool ROUND_OUT, bool QKV_MODE>
__global__ __launch_bounds__(256, 2)
void gemm256(const float* __restrict__ A, const float* __restrict__ Bm,
             const float* __restrict__ bias, float* __restrict__ C,
             float* __restrict__ Vt, int M, int N, int K)
{
    extern __shared__ __align__(16) char smc[];
    float* smf = (float*)smc;
    const uint32_t sb = smem_u32(smc);

    const int tid  = threadIdx.x;
    const int lane = tid & 31;
    const int wid  = tid >> 5;
    const int wm   = wid >> 2;          // 0..1 -> 64 m-rows
    const int wn   = wid & 3;           // 0..3 -> 64 n-rows
    const int grp  = lane >> 2;
    const int qid  = lane & 3;

    const int bm = blockIdx.y * 128;
    const int bn = blockIdx.x * 256;

    const float* AgBase = A  + (size_t)bm * K;
    const float* BgBase = Bm + (size_t)bn * K;

    auto issue_stage = [&](int stage, int buf) {
        const int k0 = stage * 16;
        const uint32_t sA = sb + (uint32_t)buf * (W_STGFL * 4);
        const uint32_t sB = sA + W_AFL * 4;
#pragma unroll
        for (int i = 0; i < 2; i++) {               // A: 512 float4 slots
            const int slot = tid + 256 * i;
            const int row = slot >> 2, col = (slot & 3) * 4;
            cp_async16(sA + (uint32_t)(row * ASTR + col) * 4,
                       AgBase + (size_t)row * K + k0 + col);
        }
#pragma unroll
        for (int i = 0; i < 4; i++) {               // B: 1024 float4 slots
            const int slot = tid + 256 * i;
            const int row = slot >> 2, col = (slot & 3) * 4;
            cp_async16(sB + (uint32_t)(row * ASTR + col) * 4,
                       BgBase + (size_t)row * K + k0 + col);
        }
        asm volatile("cp.async.commit_group;" ::: "memory");
    };

    float acc[4][8][4];
#pragma unroll
    for (int i = 0; i < 4; i++)
#pragma unroll
        for (int j = 0; j < 8; j++)
#pragma unroll
            for (int r = 0; r < 4; r++) acc[i][j][r] = 0.f;

    const int KT = K / 16;

    issue_stage(0, 0);
    issue_stage(1, 1);

    for (int kt = 0; kt < KT; kt++) {
        const int buf = kt % W_NST;

        if (kt + 1 < KT)
            asm volatile("cp.async.wait_group 1;" ::: "memory");
        else
            asm volatile("cp.async.wait_group 0;" ::: "memory");
        __syncthreads();

        if (kt + 2 < KT)
            issue_stage(kt + 2, (kt + 2) % W_NST);

        const float* Asb = smf + (size_t)buf * W_STGFL;
        const float* Bsb = Asb + W_AFL;

#pragma unroll
        for (int s = 0; s < 2; s++) {
            float a[4][4];
#pragma unroll
            for (int mf = 0; mf < 4; mf++) {
                const int row = wm * 64 + mf * 16 + grp;
                const float2 lo = *(const float2*)&Asb[row * ASTR + s * 8 + 2 * qid];
                const float2 hi = *(const float2*)&Asb[(row + 8) * ASTR + s * 8 + 2 * qid];
                a[mf][0] = lo.x; a[mf][1] = hi.x; a[mf][2] = lo.y; a[mf][3] = hi.y;
            }
            float b[8][2];
#pragma unroll
            for (int nf = 0; nf < 8; nf++) {
                const int row = wn * 64 + nf * 8 + grp;
                const float2 bv = *(const float2*)&Bsb[row * ASTR + s * 8 + 2 * qid];
                b[nf][0] = bv.x; b[nf][1] = bv.y;
            }
#pragma unroll
            for (int mf = 0; mf < 4; mf++)
#pragma unroll
                for (int nf = 0; nf < 8; nf++)
                    mma_tf32(acc[mf][nf], a[mf], b[nf]);
        }
    }

    // Epilogue
    const bool isQ = QKV_MODE && (bn < D_);
    const bool isV = QKV_MODE && (bn >= 2 * D_);

#pragma unroll
    for (int mf = 0; mf < 4; mf++) {
#pragma unroll
        for (int nf = 0; nf < 8; nf++) {
            const int m0 = bm + wm * 64 + mf * 16 + grp;
            const int n0 = bn + wn * 64 + nf * 8 + 2 * qid;
            const float bx = bias[n0], by = bias[n0 + 1];
            float2 v0, v1;
            v0.x = acc[mf][nf][0] + bx; v0.y = acc[mf][nf][1] + by;
            v1.x = acc[mf][nf][2] + bx; v1.y = acc[mf][nf][3] + by;
            if (RELU) {
                v0.x = fmaxf(v0.x, 0.f); v0.y = fmaxf(v0.y, 0.f);
                v1.x = fmaxf(v1.x, 0.f); v1.y = fmaxf(v1.y, 0.f);
            }
            if (QKV_MODE && isQ) {
                v0.x *= 0.125f; v0.y *= 0.125f; v1.x *= 0.125f; v1.y *= 0.125f;
            }
            if (ROUND_OUT) {
                v0.x = to_tf32(v0.x); v0.y = to_tf32(v0.y);
                v1.x = to_tf32(v1.x); v1.y = to_tf32(v1.y);
            }
            if (QKV_MODE && isV) {
                // Vt[(b*1024 + d)*1024 + s], d = n0-2048, b = m0>>10, s = m0&1023
                const int d0i = n0 - 2 * D_;
                const int bq  = m0 >> 10;
                const int s0  = m0 & 1023;
                float* vtb = Vt + (size_t)(bq * 1024 + d0i) * S_;
                vtb[s0]            = v0.x;
                vtb[S_ + s0]       = v0.y;
                vtb[s0 + 8]        = v1.x;
                vtb[S_ + s0 + 8]   = v1.y;
            } else {
                *(float2*)&C[(size_t)m0 * N + n0]       = v0;
                *(float2*)&C[(size_t)(m0 + 8) * N + n0] = v1;
            }
        }
    }
}

// ===== 128x128 tile kernel (MLP2): 4-stage cp.async (from R7) ==============
#define STG_BYTES (128 * ASTR * 4)
#define STAGE_BYTES (2 * STG_BYTES)
#define NSTAGE 4
#define GEMM_SMEM_BYTES (NSTAGE * STAGE_BYTES)  // 98,304

__global__ __launch_bounds__(256, 2)
void gemm128(const float* __restrict__ A, const float* __restrict__ Bm,
             const float* __restrict__ bias, float* __restrict__ C,
             int M, int N, int K)
{
    extern __shared__ __align__(16) char smc[];
    float* smf = (float*)smc;
    const uint32_t sb = smem_u32(smc);

    const int tid  = threadIdx.x;
    const int lane = tid & 31;
    const int wid  = tid >> 5;
    const int wm   = wid >> 2;
    const int wn   = wid & 3;
    const int grp  = lane >> 2;
    const int qid  = lane & 3;

    const int bm = blockIdx.y * 128;
    const int bn = blockIdx.x * 128;

    const int lrow0 = tid >> 2;
    const int lc4   = (tid & 3) * 4;
    const float* AgBase = A  + (size_t)bm * K;
    const float* BgBase = Bm + (size_t)bn * K;

    auto issue_stage = [&](int stage, int buf) {
        const int k0 = stage * 16;
        const uint32_t sA = sb + (uint32_t)buf * STAGE_BYTES;
        const uint32_t sB = sA + STG_BYTES;
#pragma unroll
        for (int i = 0; i < 2; i++) {
            const int row = lrow0 + 64 * i;
            const uint32_t doff = (uint32_t)(row * ASTR + lc4) * 4;
            cp_async16(sA + doff, AgBase + (size_t)row * K + k0 + lc4);
            cp_async16(sB + doff, BgBase + (size_t)row * K + k0 + lc4);
        }
        asm volatile("cp.async.commit_group;" ::: "memory");
    };

    float acc[4][4][4];
#pragma unroll
    for (int i = 0; i < 4; i++)
#pragma unroll
        for (int j = 0; j < 4; j++)
#pragma unroll
            for (int r = 0; r < 4; r++) acc[i][j][r] = 0.f;

    const int KT = K / 16;

    issue_stage(0, 0);
    issue_stage(1, 1);
    issue_stage(2, 2);

    for (int kt = 0; kt < KT; kt++) {
        const int buf = kt & (NSTAGE - 1);

        if (kt < KT - 2)
            asm volatile("cp.async.wait_group 2;" ::: "memory");
        else if (kt == KT - 2)
            asm volatile("cp.async.wait_group 1;" ::: "memory");
        else
            asm volatile("cp.async.wait_group 0;" ::: "memory");
        __syncthreads();

        const float* Asb = smf + (size_t)buf * (STAGE_BYTES / 4);
        const float* Bsb = Asb + STG_BYTES / 4;

#pragma unroll
        for (int s = 0; s < 2; s++) {
            float a[4][4];
#pragma unroll
            for (int mf = 0; mf < 4; mf++) {
                const int row = wm * 64 + mf * 16 + grp;
                const float2 lo = *(const float2*)&Asb[row * ASTR + s * 8 + 2 * qid];
                const float2 hi = *(const float2*)&Asb[(row + 8) * ASTR + s * 8 + 2 * qid];
                a[mf][0] = lo.x; a[mf][1] = hi.x; a[mf][2] = lo.y; a[mf][3] = hi.y;
            }
            float b[4][2];
#pragma unroll
            for (int nf = 0; nf < 4; nf++) {
                const int row = wn * 32 + nf * 8 + grp;
                const float2 bv = *(const float2*)&Bsb[row * ASTR + s * 8 + 2 * qid];
                b[nf][0] = bv.x; b[nf][1] = bv.y;
            }
#pragma unroll
            for (int mf = 0; mf < 4; mf++)
#pragma unroll
                for (int nf = 0; nf < 4; nf++)
                    mma_tf32(acc[mf][nf], a[mf], b[nf]);
        }

        if (kt + 3 < KT)
            issue_stage(kt + 3, (kt + 3) & (NSTAGE - 1));
    }

#pragma unroll
    for (int mf = 0; mf < 4; mf++) {
#pragma unroll
        for (int nf = 0; nf < 4; nf++) {
            const int m0 = bm + wm * 64 + mf * 16 + grp;
            const int n0 = bn + wn * 32 + nf * 8 + 2 * qid;
            const float bx = bias[n0], by = bias[n0 + 1];
            float2 v0, v1;
            v0.x = acc[mf][nf][0] + bx; v0.y = acc[mf][nf][1] + by;
            v1.x = acc[mf][nf][2] + bx; v1.y = acc[mf][nf][3] + by;
            *(float2*)&C[(size_t)m0 * N + n0]       = v0;
            *(float2*)&C[(size_t)(m0 + 8) * N + n0] = v1;
        }
    }
}

// ---------------------------------------------------------------------------
// Tensor-core flash attention; K from packed QKV, V from g_Vt (pre-transposed).
// All operands pre-scaled/rounded upstream -> raw cp.async copies.
// ---------------------------------------------------------------------------
#define AST 68
#define QT_ 128
#define KVSTG (64 * AST * 4)                          // 17,408 B per stage
#define ATTN_SMEM_BYTES (QT_ * AST * 4 + 4 * KVSTG)   // 104,448 B

__global__ __launch_bounds__(256, 2)
void attn_tc(const float* __restrict__ QKV, const float* __restrict__ VtG,
             const int* __restrict__ mask, float* __restrict__ O)
{
    extern __shared__ float smf[];
    float* Qs = smf;                              // [128][AST]
    const uint32_t sb   = smem_u32(smf);
    const uint32_t sbK  = sb + QT_ * AST * 4;     // 2 stages of K [key][d]
    const uint32_t sbV  = sbK + 2 * KVSTG;        // 2 stages of V^T [d][key]

    const int tid  = threadIdx.x;
    const int lane = tid & 31;
    const int wid  = tid >> 5;
    const int grp  = lane >> 2;
    const int qid  = lane & 3;

    const int qt = blockIdx.x;
    const int bh = blockIdx.y;
    const int b  = bh >> 4;
    const int h  = bh & 15;
    const int q0 = qt * QT_;

    const int LDQ = 3 * D_;
    const float* Qb = QKV + (size_t)b * S_ * LDQ + (size_t)h * HD_;
    const float* Kb = Qb + D_;
    const float* Vb = VtG + (size_t)bh * HD_ * S_;   // [d][s]

    auto issue_kv = [&](int kt, int buf) {
        const int k0g = kt * 64;
        const uint32_t sK = sbK + (uint32_t)buf * KVSTG;
        const uint32_t sV = sbV + (uint32_t)buf * KVSTG;
#pragma unroll
        for (int i = 0; i < 4; i++) {
            const int c   = tid + 256 * i;        // 0..1023
            const int row = c >> 4;               // 0..63
            const int col = (c & 15) * 4;         // 0..60
            const uint32_t doff = (uint32_t)(row * AST + col) * 4;
            cp_async16(sK + doff, Kb + (size_t)(k0g + row) * LDQ + col);
            cp_async16(sV + doff, Vb + (size_t)row * S_ + k0g + col);
        }
        asm volatile("cp.async.commit_group;" ::: "memory");
    };

    issue_kv(0, 0);

    // Q tile: raw copy (pre-scaled + rounded upstream)
    {
        const int r  = tid >> 1;
        const int c0 = (tid & 1) * 32;
        const float* src = Qb + (size_t)(q0 + r) * LDQ + c0;
        float* dst = &Qs[r * AST + c0];
#pragma unroll
        for (int i = 0; i < 8; i++)
            *(float4*)(dst + i * 4) = *(const float4*)(src + i * 4);
    }

    const int qrow0 = wid * 16 + grp;
    const int* mrow0 = mask + (size_t)(b * S_ + q0 + qrow0) * S_;
    const int* mrow1 = mrow0 + 8 * S_;

    float mi0 = -1e30f, mi1 = -1e30f, li0 = 0.f, li1 = 0.f;
    float o[8][4];
#pragma unroll
    for (int nf = 0; nf < 8; nf++)
#pragma unroll
        for (int r = 0; r < 4; r++) o[nf][r] = 0.f;

    for (int kt = 0; kt < S_ / 64; kt++) {
        const int buf = kt & 1;
        const int k0  = kt * 64;

        asm volatile("cp.async.wait_group 0;" ::: "memory");
        __syncthreads();

        if (kt + 1 < S_ / 64)
            issue_kv(kt + 1, buf ^ 1);

        const float* Ksb = smf + (QT_ * AST) + (size_t)buf * (KVSTG / 4);
        const float* Vsb = smf + (QT_ * AST) + 2 * (KVSTG / 4) + (size_t)buf * (KVSTG / 4);

        // ---- QK^T ----
        float c[8][4];
#pragma unroll
        for (int nf = 0; nf < 8; nf++)
#pragma unroll
            for (int r = 0; r < 4; r++) c[nf][r] = 0.f;

#pragma unroll
        for (int s = 0; s < 8; s++) {
            const float2 alo = *(const float2*)&Qs[qrow0 * AST + s * 8 + 2 * qid];
            const float2 ahi = *(const float2*)&Qs[(qrow0 + 8) * AST + s * 8 + 2 * qid];
            float a[4] = { alo.x, ahi.x, alo.y, ahi.y };
#pragma unroll
            for (int nf = 0; nf < 8; nf++) {
                const float2 bv = *(const float2*)&Ksb[(nf * 8 + grp) * AST + s * 8 + 2 * qid];
                mma_tf32(c[nf], a, (const float*)&bv);
            }
        }

        // ---- mask ----
#pragma unroll
        for (int nf = 0; nf < 8; nf++) {
            const int kc = k0 + nf * 8 + 2 * qid;
            const int2 m0 = *(const int2*)&mrow0[kc];
            const int2 m1 = *(const int2*)&mrow1[kc];
            if (m0.x == 0) c[nf][0] = -1e8f;
            if (m0.y == 0) c[nf][1] = -1e8f;
            if (m1.x == 0) c[nf][2] = -1e8f;
            if (m1.y == 0) c[nf][3] = -1e8f;
        }

        // ---- online softmax on fragments ----
        float mx0 = -1e30f, mx1 = -1e30f;
#pragma unroll
        for (int nf = 0; nf < 8; nf++) {
            mx0 = fmaxf(mx0, fmaxf(c[nf][0], c[nf][1]));
            mx1 = fmaxf(mx1, fmaxf(c[nf][2], c[nf][3]));
        }
        mx0 = fmaxf(mx0, __shfl_xor_sync(0xffffffffu, mx0, 1));
        mx0 = fmaxf(mx0, __shfl_xor_sync(0xffffffffu, mx0, 2));
        mx1 = fmaxf(mx1, __shfl_xor_sync(0xffffffffu, mx1, 1));
        mx1 = fmaxf(mx1, __shfl_xor_sync(0xffffffffu, mx1, 2));

        const float mn0 = fmaxf(mi0, mx0);
        const float mn1 = fmaxf(mi1, mx1);
        const float al0 = __expf(mi0 - mn0);
        const float al1 = __expf(mi1 - mn1);

        float sum0 = 0.f, sum1 = 0.f;
#pragma unroll
        for (int nf = 0; nf < 8; nf++) {
            float e;
            e = __expf(c[nf][0] - mn0); sum0 += e; c[nf][0] = to_tf32(e);
            e = __expf(c[nf][1] - mn0); sum0 += e; c[nf][1] = to_tf32(e);
            e = __expf(c[nf][2] - mn1); sum1 += e; c[nf][2] = to_tf32(e);
            e = __expf(c[nf][3] - mn1); sum1 += e; c[nf][3] = to_tf32(e);
        }
        sum0 += __shfl_xor_sync(0xffffffffu, sum0, 1);
        sum0 += __shfl_xor_sync(0xffffffffu, sum0, 2);
        sum1 += __shfl_xor_sync(0xffffffffu, sum1, 1);
        sum1 += __shfl_xor_sync(0xffffffffu, sum1, 2);

        li0 = li0 * al0 + sum0;  mi0 = mn0;
        li1 = li1 * al1 + sum1;  mi1 = mn1;

#pragma unroll
        for (int nf = 0; nf < 8; nf++) {
            o[nf][0] *= al0; o[nf][1] *= al0;
            o[nf][2] *= al1; o[nf][3] *= al1;
        }

        // ---- PV: V^T in smem [d][key]; B-fragment is one LDS.64 ----
#pragma unroll
        for (int s = 0; s < 8; s++) {
            float a[4] = { c[s][0], c[s][2], c[s][1], c[s][3] };
            const int kr = s * 8 + 2 * qid;
#pragma unroll
            for (int nf = 0; nf < 8; nf++) {
                const float2 bv = *(const float2*)&Vsb[(nf * 8 + grp) * AST + kr];
                mma_tf32(o[nf], a, (const float*)&bv);
            }
        }
    }

    // ---- finalize ----
    const float inv0 = 1.0f / li0;
    const float inv1 = 1.0f / li1;
    const size_t row0g = (size_t)(b * S_ + q0 + qrow0) * D_ + (size_t)h * HD_;
    const size_t row1g = row0g + (size_t)8 * D_;
#pragma unroll
    for (int nf = 0; nf < 8; nf++) {
        const int d0 = nf * 8 + 2 * qid;
        float2 v0, v1;
        v0.x = to_tf32(o[nf][0] * inv0); v0.y = to_tf32(o[nf][1] * inv0);
        v1.x = to_tf32(o[nf][2] * inv1); v1.y = to_tf32(o[nf][3] * inv1);
        *(float2*)&O[row0g + d0] = v0;
        *(float2*)&O[row1g + d0] = v1;
    }
}

// ---------------------------------------------------------------------------
// Launch.  Inputs: x, Wq, bq, Wk, bk, Wv, bv, W1, b1, W2, b2, mask
// ---------------------------------------------------------------------------
extern "C" void kernel_launch(void* const* d_in, const int* in_sizes, int n_in,
                              void* d_out, int out_size)
{
    const float* x    = (const float*)d_in[0];
    const float* Wq   = (const float*)d_in[1];
    const float* bq   = (const float*)d_in[2];
    const float* Wk   = (const float*)d_in[3];
    const float* bk   = (const float*)d_in[4];
    const float* Wv   = (const float*)d_in[5];
    const float* bv   = (const float*)d_in[6];
    const float* W1   = (const float*)d_in[7];
    const float* b1   = (const float*)d_in[8];
    const float* W2   = (const float*)d_in[9];
    const float* b2   = (const float*)d_in[10];
    const int*   mask = (const int*)d_in[11];
    float*       out  = (float*)d_out;

    float *Xp, *Wqkvp, *bqkvp, *W1p, *W2p, *QKVp, *Vtp, *Cp, *Hp;
    cudaGetSymbolAddress((void**)&Xp,    g_X);
    cudaGetSymbolAddress((void**)&Wqkvp, g_Wqkv);
    cudaGetSymbolAddress((void**)&bqkvp, g_bqkv);
    cudaGetSymbolAddress((void**)&W1p,   g_W1r);
    cudaGetSymbolAddress((void**)&W2p,   g_W2r);
    cudaGetSymbolAddress((void**)&QKVp,  g_QKV);
    cudaGetSymbolAddress((void**)&Vtp,   g_Vt);
    cudaGetSymbolAddress((void**)&Cp,    g_C);
    cudaGetSymbolAddress((void**)&Hp,    g_Hid);

    cudaFuncSetAttribute(attn_tc,
                         cudaFuncAttributeMaxDynamicSharedMemorySize, ATTN_SMEM_BYTES);
    cudaFuncSetAttribute((const void*)gemm256<false, true, true>,
                         cudaFuncAttributeMaxDynamicSharedMemorySize, GEMM256_SMEM);
    cudaFuncSetAttribute((const void*)gemm256<true, true, false>,
                         cudaFuncAttributeMaxDynamicSharedMemorySize, GEMM256_SMEM);
    cudaFuncSetAttribute(gemm128,
                         cudaFuncAttributeMaxDynamicSharedMemorySize, GEMM_SMEM_BYTES);

    const dim3 blk(256);
    const int T = 256;

    // ---- prep: fused tf32 rounding of x + all weights ----
    RoundSegs P;
    P.src[0] = x;  P.dst[0] = Xp;
    P.src[1] = Wq; P.dst[1] = Wqkvp;
    P.src[2] = Wk; P.dst[2] = Wqkvp + (size_t)D_ * D_;
    P.src[3] = Wv; P.dst[3] = Wqkvp + (size_t)2 * D_ * D_;
    P.src[4] = W1; P.dst[4] = W1p;
    P.src[5] = W2; P.dst[5] = W2p;
    const int n4s[6] = { M_ * D_ / 4, D_ * D_ / 4, D_ * D_ / 4, D_ * D_ / 4,
                         2 * D_ * D_ / 4, 2 * D_ * D_ / 4 };
    P.cum[0] = 0;
    for (int j = 0; j < 6; j++) P.cum[j + 1] = P.cum[j] + n4s[j];
    round_all<<<(P.cum[6] + T - 1) / T, T>>>(P);
    concat_bias<<<(3 * D_ + T - 1) / T, T>>>(bq, bk, bv, bqkvp);

    // ---- fused QKV projection (Q pre-scale, round, V -> Vt transposed) ----
    gemm256<false, true, true><<<dim3(3 * D_ / 256, M_ / 128), blk, GEMM256_SMEM>>>(
        Xp, Wqkvp, bqkvp, QKVp, Vtp, M_, 3 * D_, D_);

    // ---- attention ----
    attn_tc<<<dim3(S_ / QT_, B_ * H_), blk, ATTN_SMEM_BYTES>>>(QKVp, Vtp, mask, Cp);

    // ---- MLP ----
    gemm256<true, true, false><<<dim3(2 * D_ / 256, M_ / 128), blk, GEMM256_SMEM>>>(
        Cp, W1p, b1, Hp, (float*)nullptr, M_, 2 * D_, D_);
    gemm128<<<dim3(D_ / 128, M_ / 128), blk, GEMM_SMEM_BYTES>>>(
        Hp, W2p, b2, out, M_, D_, 2 * D_);
}

// round 9
// speedup vs baseline: 4.2918x; 4.2918x over previous
#include <cuda_runtime.h>
#include <cuda_fp16.h>
#include <stdint.h>

#define B_  4
#define S_  1024
#define D_  1024
#define H_  16
#define HD_ 64
#define M_  (B_ * S_)     // 4096

// ---------------------------------------------------------------------------
// Scratch (device globals)
// ---------------------------------------------------------------------------
__device__ __align__(16) __half g_Xh   [(size_t)M_ * D_];        // x, k-permuted fp16
__device__ __align__(16) __half g_Wqkvh[(size_t)3 * D_ * D_];    // Wq|Wk|Wv
__device__ __align__(16) __half g_W1h  [(size_t)2 * D_ * D_];
__device__ __align__(16) __half g_W2h  [(size_t)2 * D_ * D_];
__device__ __align__(16) __half g_Ch   [(size_t)M_ * D_];        // ctx, permuted fp16
__device__ __align__(16) __half g_Hh   [(size_t)M_ * 2 * D_];    // hidden, permuted fp16
__device__ __align__(16) float  g_QKV  [(size_t)M_ * 3 * D_];    // fp32 for attention
__device__ __align__(16) float  g_bqkv [3 * D_];

// ---------------------------------------------------------------------------
__device__ __forceinline__ float to_tf32(float x) {
    uint32_t u;
    asm("cvt.rna.tf32.f32 %0, %1;" : "=r"(u) : "f"(x));
    return __uint_as_float(u);
}

// tf32 m16n8k8 (attention only)
__device__ __forceinline__ void mma_tf32(float* c, const float* a, const float* b) {
    asm volatile(
        "mma.sync.aligned.m16n8k8.row.col.f32.tf32.tf32.f32 "
        "{%0,%1,%2,%3}, {%4,%5,%6,%7}, {%8,%9}, {%0,%1,%2,%3};\n"
        : "+f"(c[0]), "+f"(c[1]), "+f"(c[2]), "+f"(c[3])
        : "r"(__float_as_uint(a[0])), "r"(__float_as_uint(a[1])),
          "r"(__float_as_uint(a[2])), "r"(__float_as_uint(a[3])),
          "r"(__float_as_uint(b[0])), "r"(__float_as_uint(b[1])));
}

// fp16 m16n8k16 (GEMMs)
__device__ __forceinline__ void mma_f16(float* c, const uint32_t* a, const uint32_t* b) {
    asm volatile(
        "mma.sync.aligned.m16n8k16.row.col.f32.f16.f16.f32 "
        "{%0,%1,%2,%3}, {%4,%5,%6,%7}, {%8,%9}, {%0,%1,%2,%3};\n"
        : "+f"(c[0]), "+f"(c[1]), "+f"(c[2]), "+f"(c[3])
        : "r"(a[0]), "r"(a[1]), "r"(a[2]), "r"(a[3]), "r"(b[0]), "r"(b[1]));
}

__device__ __forceinline__ uint32_t smem_u32(const void* p) {
    uint32_t a;
    asm("{ .reg .u64 t; cvta.to.shared.u64 t, %1; cvt.u32.u64 %0, t; }"
        : "=r"(a) : "l"(p));
    return a;
}

__device__ __forceinline__ void cp_async16(uint32_t dst, const void* src) {
    asm volatile("cp.async.cg.shared.global [%0], [%1], 16;"
                 :: "r"(dst), "l"(src) : "memory");
}

__device__ __forceinline__ uint32_t packh2(float x, float y) {
    __half2 h = __floats2half2_rn(x, y);
    return *(uint32_t*)&h;
}

// logical (even) n -> permuted phys position within its 16-group
__device__ __forceinline__ int permn(int n0) {
    return (n0 & ~15) | (((n0 >> 1) & 3) << 2) | ((n0 & 8) >> 2);
}

// ---------------------------------------------------------------------------
// Prep: fp32 -> k-permuted fp16, 16-element groups.
// phys halves [4q..4q+3] = logical {2q, 2q+1, 2q+8, 2q+9}
// ---------------------------------------------------------------------------
struct HSegs {
    const float* src[6];
    __half*      dst[6];
    int          cum[7];    // cumulative 16-elt group counts
};

__global__ void round_half_all(HSegs P) {
    const int i = blockIdx.x * blockDim.x + threadIdx.x;
    if (i >= P.cum[6]) return;
#pragma unroll
    for (int j = 0; j < 6; j++) {
        if (i < P.cum[j + 1]) {
            const int g = i - P.cum[j];
            const float4* s = (const float4*)P.src[j] + (size_t)g * 4;
            float l[16];
            *(float4*)&l[0]  = s[0];
            *(float4*)&l[4]  = s[1];
            *(float4*)&l[8]  = s[2];
            *(float4*)&l[12] = s[3];
            uint4 o0, o1;
            o0.x = packh2(l[0],  l[1]);  o0.y = packh2(l[8],  l[9]);
            o0.z = packh2(l[2],  l[3]);  o0.w = packh2(l[10], l[11]);
            o1.x = packh2(l[4],  l[5]);  o1.y = packh2(l[12], l[13]);
            o1.z = packh2(l[6],  l[7]);  o1.w = packh2(l[14], l[15]);
            uint4* d = (uint4*)(P.dst[j] + (size_t)g * 16);
            d[0] = o0; d[1] = o1;
            return;
        }
    }
}

__global__ void concat_bias(const float* __restrict__ a, const float* __restrict__ b,
                            const float* __restrict__ c, float* __restrict__ dst) {
    const int i = blockIdx.x * blockDim.x + threadIdx.x;
    if (i < 3 * D_)
        dst[i] = (i < D_) ? a[i] : ((i < 2 * D_) ? b[i - D_] : c[i - 2 * D_]);
}

// ---------------------------------------------------------------------------
// fp16 tensor-core GEMM: C[m,n] = sum_k A[m,k]*B[n,k] + bias[n]
// 128x128 tile, K-stage 32, 4-stage cp.async, warp tile 64x32.
// Smem row = 32 data halves + 16 pad = 48 halves (96 B): fragment LDS.64
// conflict-free. MODE: 0 = QKV (fp32 out, Q prescale, tf32 round),
// 1 = MLP1 (ReLU, permuted-half out), 2 = MLP2 (plain fp32 out).
// ---------------------------------------------------------------------------
#define HROWB 96
#define HSTG_B (128 * HROWB)        // 12,288 B per matrix per stage
#define HSTAGE_B (2 * HSTG_B)       // 24,576
#define HNST 4
#define HGEMM_SMEM (HNST * HSTAGE_B)  // 98,304

template <int MODE>
__global__ __launch_bounds__(256, 2)
void gemm_h(const __half* __restrict__ A, const __half* __restrict__ Bm,
            const float* __restrict__ bias, float* __restrict__ Cf,
            __half* __restrict__ Ch, int M, int N, int K)
{
    extern __shared__ __align__(16) char smc[];
    const uint32_t sb = smem_u32(smc);

    const int tid  = threadIdx.x;
    const int lane = tid & 31;
    const int wid  = tid >> 5;
    const int wm   = wid >> 2;
    const int wn   = wid & 3;
    const int grp  = lane >> 2;
    const int qid  = lane & 3;

    const int bm = blockIdx.y * 128;
    const int bn = blockIdx.x * 128;

    const __half* AgBase = A  + (size_t)bm * K;
    const __half* BgBase = Bm + (size_t)bn * K;

    auto issue_stage = [&](int stage, int buf) {
        const int k0 = stage * 32;
        const uint32_t sA = sb + (uint32_t)buf * HSTAGE_B;
        const uint32_t sB = sA + HSTG_B;
#pragma unroll
        for (int i = 0; i < 2; i++) {
            const int idx = tid + 256 * i;       // 0..511
            const int row = idx >> 2;            // 0..127
            const int c   = idx & 3;             // 16B chunk = 8 halves
            const uint32_t doff = (uint32_t)row * HROWB + (uint32_t)c * 16;
            cp_async16(sA + doff, AgBase + (size_t)row * K + k0 + c * 8);
            cp_async16(sB + doff, BgBase + (size_t)row * K + k0 + c * 8);
        }
        asm volatile("cp.async.commit_group;" ::: "memory");
    };

    float acc[4][4][4];
#pragma unroll
    for (int i = 0; i < 4; i++)
#pragma unroll
        for (int j = 0; j < 4; j++)
#pragma unroll
            for (int r = 0; r < 4; r++) acc[i][j][r] = 0.f;

    const int KT = K / 32;

    issue_stage(0, 0);
    issue_stage(1, 1);
    issue_stage(2, 2);

    for (int kt = 0; kt < KT; kt++) {
        const int buf = kt & (HNST - 1);

        if (kt < KT - 2)
            asm volatile("cp.async.wait_group 2;" ::: "memory");
        else if (kt == KT - 2)
            asm volatile("cp.async.wait_group 1;" ::: "memory");
        else
            asm volatile("cp.async.wait_group 0;" ::: "memory");
        __syncthreads();

        const char* Asb = smc + (size_t)buf * HSTAGE_B;
        const char* Bsb = Asb + HSTG_B;

#pragma unroll
        for (int s = 0; s < 2; s++) {            // two k16 steps per stage
            uint32_t a[4][4];
#pragma unroll
            for (int mf = 0; mf < 4; mf++) {
                const int row = wm * 64 + mf * 16 + grp;
                const uint2 lo = *(const uint2*)(Asb + row * HROWB + s * 32 + qid * 8);
                const uint2 hi = *(const uint2*)(Asb + (row + 8) * HROWB + s * 32 + qid * 8);
                a[mf][0] = lo.x; a[mf][1] = hi.x; a[mf][2] = lo.y; a[mf][3] = hi.y;
            }
            uint32_t b[4][2];
#pragma unroll
            for (int nf = 0; nf < 4; nf++) {
                const int row = wn * 32 + nf * 8 + grp;
                const uint2 bv = *(const uint2*)(Bsb + row * HROWB + s * 32 + qid * 8);
                b[nf][0] = bv.x; b[nf][1] = bv.y;
            }
#pragma unroll
            for (int mf = 0; mf < 4; mf++)
#pragma unroll
                for (int nf = 0; nf < 4; nf++)
                    mma_f16(acc[mf][nf], a[mf], b[nf]);
        }

        if (kt + 3 < KT)
            issue_stage(kt + 3, (kt + 3) & (HNST - 1));
    }

    // ---- Epilogue ----
#pragma unroll
    for (int mf = 0; mf < 4; mf++) {
#pragma unroll
        for (int nf = 0; nf < 4; nf++) {
            const int m0 = bm + wm * 64 + mf * 16 + grp;
            const int n0 = bn + wn * 32 + nf * 8 + 2 * qid;
            const float bx = bias[n0], by = bias[n0 + 1];
            float2 v0, v1;
            v0.x = acc[mf][nf][0] + bx; v0.y = acc[mf][nf][1] + by;
            v1.x = acc[mf][nf][2] + bx; v1.y = acc[mf][nf][3] + by;

            if (MODE == 0) {
                // QKV: Q columns pre-scaled by 1/8, all tf32-rounded, fp32 out
                if (n0 < D_) {
                    v0.x *= 0.125f; v0.y *= 0.125f;
                    v1.x *= 0.125f; v1.y *= 0.125f;
                }
                v0.x = to_tf32(v0.x); v0.y = to_tf32(v0.y);
                v1.x = to_tf32(v1.x); v1.y = to_tf32(v1.y);
                *(float2*)&Cf[(size_t)m0 * N + n0]       = v0;
                *(float2*)&Cf[(size_t)(m0 + 8) * N + n0] = v1;
            } else if (MODE == 1) {
                // MLP1: ReLU, permuted-half out
                v0.x = fmaxf(v0.x, 0.f); v0.y = fmaxf(v0.y, 0.f);
                v1.x = fmaxf(v1.x, 0.f); v1.y = fmaxf(v1.y, 0.f);
                const int pn = permn(n0);
                *(uint32_t*)&Ch[(size_t)m0 * N + pn]       = packh2(v0.x, v0.y);
                *(uint32_t*)&Ch[(size_t)(m0 + 8) * N + pn] = packh2(v1.x, v1.y);
            } else {
                // MLP2: plain fp32 out
                *(float2*)&Cf[(size_t)m0 * N + n0]       = v0;
                *(float2*)&Cf[(size_t)(m0 + 8) * N + n0] = v1;
            }
        }
    }
}

// ---------------------------------------------------------------------------
// Tensor-core flash attention (tf32) — R7 verbatim, except ctx written as
// permuted fp16 for the fp16 MLP1.
// ---------------------------------------------------------------------------
#define AST 68
#define QT_ 128
#define KVSTG (64 * AST * 4)
#define ATTN_SMEM_BYTES (QT_ * AST * 4 + 4 * KVSTG)   // 104,448 B

__global__ __launch_bounds__(256, 2)
void attn_tc(const float* __restrict__ QKV, const int* __restrict__ mask,
             __half* __restrict__ O)
{
    extern __shared__ float smf[];
    float* Qs = smf;
    const uint32_t sb   = smem_u32(smf);
    const uint32_t sbK  = sb + QT_ * AST * 4;
    const uint32_t sbV  = sbK + 2 * KVSTG;

    const int tid  = threadIdx.x;
    const int lane = tid & 31;
    const int wid  = tid >> 5;
    const int grp  = lane >> 2;
    const int qid  = lane & 3;

    const int qt = blockIdx.x;
    const int bh = blockIdx.y;
    const int b  = bh >> 4;
    const int h  = bh & 15;
    const int q0 = qt * QT_;

    const int LDQ = 3 * D_;
    const float* Qb = QKV + (size_t)b * S_ * LDQ + (size_t)h * HD_;
    const float* Kb = Qb + D_;
    const float* Vb = Qb + 2 * D_;

    auto issue_kv = [&](int kt, int buf) {
        const int k0g = kt * 64;
        const uint32_t sK = sbK + (uint32_t)buf * KVSTG;
        const uint32_t sV = sbV + (uint32_t)buf * KVSTG;
#pragma unroll
        for (int i = 0; i < 4; i++) {
            const int c   = tid + 256 * i;
            const int row = c >> 4;
            const int col = (c & 15) * 4;
            const uint32_t doff = (uint32_t)(row * AST + col) * 4;
            cp_async16(sK + doff, Kb + (size_t)(k0g + row) * LDQ + col);
            cp_async16(sV + doff, Vb + (size_t)(k0g + row) * LDQ + col);
        }
        asm volatile("cp.async.commit_group;" ::: "memory");
    };

    issue_kv(0, 0);

    {
        const int r  = tid >> 1;
        const int c0 = (tid & 1) * 32;
        const float* src = Qb + (size_t)(q0 + r) * LDQ + c0;
        float* dst = &Qs[r * AST + c0];
#pragma unroll
        for (int i = 0; i < 8; i++)
            *(float4*)(dst + i * 4) = *(const float4*)(src + i * 4);
    }

    const int qrow0 = wid * 16 + grp;
    const int* mrow0 = mask + (size_t)(b * S_ + q0 + qrow0) * S_;
    const int* mrow1 = mrow0 + 8 * S_;

    float mi0 = -1e30f, mi1 = -1e30f, li0 = 0.f, li1 = 0.f;
    float o[8][4];
#pragma unroll
    for (int nf = 0; nf < 8; nf++)
#pragma unroll
        for (int r = 0; r < 4; r++) o[nf][r] = 0.f;

    for (int kt = 0; kt < S_ / 64; kt++) {
        const int buf = kt & 1;
        const int k0  = kt * 64;

        asm volatile("cp.async.wait_group 0;" ::: "memory");
        __syncthreads();

        if (kt + 1 < S_ / 64)
            issue_kv(kt + 1, buf ^ 1);

        const float* Ksb = smf + (QT_ * AST) + (size_t)buf * (KVSTG / 4);
        const float* Vsb = smf + (QT_ * AST) + 2 * (KVSTG / 4) + (size_t)buf * (KVSTG / 4);

        float c[8][4];
#pragma unroll
        for (int nf = 0; nf < 8; nf++)
#pragma unroll
            for (int r = 0; r < 4; r++) c[nf][r] = 0.f;

#pragma unroll
        for (int s = 0; s < 8; s++) {
            const float2 alo = *(const float2*)&Qs[qrow0 * AST + s * 8 + 2 * qid];
            const float2 ahi = *(const float2*)&Qs[(qrow0 + 8) * AST + s * 8 + 2 * qid];
            float a[4] = { alo.x, ahi.x, alo.y, ahi.y };
#pragma unroll
            for (int nf = 0; nf < 8; nf++) {
                const float2 bv = *(const float2*)&Ksb[(nf * 8 + grp) * AST + s * 8 + 2 * qid];
                mma_tf32(c[nf], a, (const float*)&bv);
            }
        }

#pragma unroll
        for (int nf = 0; nf < 8; nf++) {
            const int kc = k0 + nf * 8 + 2 * qid;
            const int2 m0 = *(const int2*)&mrow0[kc];
            const int2 m1 = *(const int2*)&mrow1[kc];
            if (m0.x == 0) c[nf][0] = -1e8f;
            if (m0.y == 0) c[nf][1] = -1e8f;
            if (m1.x == 0) c[nf][2] = -1e8f;
            if (m1.y == 0) c[nf][3] = -1e8f;
        }

        float mx0 = -1e30f, mx1 = -1e30f;
#pragma unroll
        for (int nf = 0; nf < 8; nf++) {
            mx0 = fmaxf(mx0, fmaxf(c[nf][0], c[nf][1]));
            mx1 = fmaxf(mx1, fmaxf(c[nf][2], c[nf][3]));
        }
        mx0 = fmaxf(mx0, __shfl_xor_sync(0xffffffffu, mx0, 1));
        mx0 = fmaxf(mx0, __shfl_xor_sync(0xffffffffu, mx0, 2));
        mx1 = fmaxf(mx1, __shfl_xor_sync(0xffffffffu, mx1, 1));
        mx1 = fmaxf(mx1, __shfl_xor_sync(0xffffffffu, mx1, 2));

        const float mn0 = fmaxf(mi0, mx0);
        const float mn1 = fmaxf(mi1, mx1);
        const float al0 = __expf(mi0 - mn0);
        const float al1 = __expf(mi1 - mn1);

        float sum0 = 0.f, sum1 = 0.f;
#pragma unroll
        for (int nf = 0; nf < 8; nf++) {
            float e;
            e = __expf(c[nf][0] - mn0); sum0 += e; c[nf][0] = to_tf32(e);
            e = __expf(c[nf][1] - mn0); sum0 += e; c[nf][1] = to_tf32(e);
            e = __expf(c[nf][2] - mn1); sum1 += e; c[nf][2] = to_tf32(e);
            e = __expf(c[nf][3] - mn1); sum1 += e; c[nf][3] = to_tf32(e);
        }
        sum0 += __shfl_xor_sync(0xffffffffu, sum0, 1);
        sum0 += __shfl_xor_sync(0xffffffffu, sum0, 2);
        sum1 += __shfl_xor_sync(0xffffffffu, sum1, 1);
        sum1 += __shfl_xor_sync(0xffffffffu, sum1, 2);

        li0 = li0 * al0 + sum0;  mi0 = mn0;
        li1 = li1 * al1 + sum1;  mi1 = mn1;

#pragma unroll
        for (int nf = 0; nf < 8; nf++) {
            o[nf][0] *= al0; o[nf][1] *= al0;
            o[nf][2] *= al1; o[nf][3] *= al1;
        }

#pragma unroll
        for (int s = 0; s < 8; s++) {
            float a[4] = { c[s][0], c[s][2], c[s][1], c[s][3] };
            const int kr = s * 8 + 2 * qid;
#pragma unroll
            for (int nf = 0; nf < 8; nf++) {
                float bb[2];
                bb[0] = Vsb[kr * AST + nf * 8 + grp];
                bb[1] = Vsb[(kr + 1) * AST + nf * 8 + grp];
                mma_tf32(o[nf], a, bb);
            }
        }
    }

    // ---- finalize: ctx as permuted fp16 (consumed by fp16 MLP1) ----
    const float inv0 = 1.0f / li0;
    const float inv1 = 1.0f / li1;
    __half* row0g = O + (size_t)(b * S_ + q0 + qrow0) * D_ + (size_t)h * HD_;
    __half* row1g = row0g + (size_t)8 * D_;
#pragma unroll
    for (int nf = 0; nf < 8; nf++) {
        const int d0 = nf * 8 + 2 * qid;
        const int pd = (d0 & 48) | (((d0 >> 1) & 3) << 2) | ((d0 & 8) >> 2);
        *(uint32_t*)(row0g + pd) = packh2(o[nf][0] * inv0, o[nf][1] * inv0);
        *(uint32_t*)(row1g + pd) = packh2(o[nf][2] * inv1, o[nf][3] * inv1);
    }
}

// ---------------------------------------------------------------------------
// Launch.  Inputs: x, Wq, bq, Wk, bk, Wv, bv, W1, b1, W2, b2, mask
// ---------------------------------------------------------------------------
extern "C" void kernel_launch(void* const* d_in, const int* in_sizes, int n_in,
                              void* d_out, int out_size)
{
    const float* x    = (const float*)d_in[0];
    const float* Wq   = (const float*)d_in[1];
    const float* bq   = (const float*)d_in[2];
    const float* Wk   = (const float*)d_in[3];
    const float* bk   = (const float*)d_in[4];
    const float* Wv   = (const float*)d_in[5];
    const float* bv   = (const float*)d_in[6];
    const float* W1   = (const float*)d_in[7];
    const float* b1   = (const float*)d_in[8];
    const float* W2   = (const float*)d_in[9];
    const float* b2   = (const float*)d_in[10];
    const int*   mask = (const int*)d_in[11];
    float*       out  = (float*)d_out;

    __half *Xh, *Wqkvh, *W1h, *W2h, *Chp, *Hhp;
    float *QKVp, *bqkvp;
    cudaGetSymbolAddress((void**)&Xh,    g_Xh);
    cudaGetSymbolAddress((void**)&Wqkvh, g_Wqkvh);
    cudaGetSymbolAddress((void**)&W1h,   g_W1h);
    cudaGetSymbolAddress((void**)&W2h,   g_W2h);
    cudaGetSymbolAddress((void**)&Chp,   g_Ch);
    cudaGetSymbolAddress((void**)&Hhp,   g_Hh);
    cudaGetSymbolAddress((void**)&QKVp,  g_QKV);
    cudaGetSymbolAddress((void**)&bqkvp, g_bqkv);

    cudaFuncSetAttribute(attn_tc,
                         cudaFuncAttributeMaxDynamicSharedMemorySize, ATTN_SMEM_BYTES);
    cudaFuncSetAttribute((const void*)gemm_h<0>,
                         cudaFuncAttributeMaxDynamicSharedMemorySize, HGEMM_SMEM);
    cudaFuncSetAttribute((const void*)gemm_h<1>,
                         cudaFuncAttributeMaxDynamicSharedMemorySize, HGEMM_SMEM);
    cudaFuncSetAttribute((const void*)gemm_h<2>,
                         cudaFuncAttributeMaxDynamicSharedMemorySize, HGEMM_SMEM);

    const dim3 blk(256);
    const int T = 256;

    // ---- prep: fp32 -> permuted fp16 for x and all weights ----
    HSegs P;
    P.src[0] = x;  P.dst[0] = Xh;
    P.src[1] = Wq; P.dst[1] = Wqkvh;
    P.src[2] = Wk; P.dst[2] = Wqkvh + (size_t)D_ * D_;
    P.src[3] = Wv; P.dst[3] = Wqkvh + (size_t)2 * D_ * D_;
    P.src[4] = W1; P.dst[4] = W1h;
    P.src[5] = W2; P.dst[5] = W2h;
    const int gr[6] = { M_ * D_ / 16, D_ * D_ / 16, D_ * D_ / 16, D_ * D_ / 16,
                        2 * D_ * D_ / 16, 2 * D_ * D_ / 16 };
    P.cum[0] = 0;
    for (int j = 0; j < 6; j++) P.cum[j + 1] = P.cum[j] + gr[j];
    round_half_all<<<(P.cum[6] + T - 1) / T, T>>>(P);
    concat_bias<<<(3 * D_ + T - 1) / T, T>>>(bq, bk, bv, bqkvp);

    // ---- fused QKV projection (fp16 in, fp32 out; Q prescale + tf32 round) --
    gemm_h<0><<<dim3(3 * D_ / 128, M_ / 128), blk, HGEMM_SMEM>>>(
        Xh, Wqkvh, bqkvp, QKVp, (__half*)nullptr, M_, 3 * D_, D_);

    // ---- attention (tf32; ctx out as permuted fp16) ----
    attn_tc<<<dim3(S_ / QT_, B_ * H_), blk, ATTN_SMEM_BYTES>>>(QKVp, mask, Chp);

    // ---- MLP ----
    gemm_h<1><<<dim3(2 * D_ / 128, M_ / 128), blk, HGEMM_SMEM>>>(
        Chp, W1h, b1, (float*)nullptr, Hhp, M_, 2 * D_, D_);
    gemm_h<2><<<dim3(D_ / 128, M_ / 128), blk, HGEMM_SMEM>>>(
        Hhp, W2h, b2, out, (__half*)nullptr, M_, D_, 2 * D_);
}

// round 10
// speedup vs baseline: 5.5383x; 1.2904x over previous
#include <cuda_runtime.h>
#include <cuda_fp16.h>
#include <stdint.h>

#define B_  4
#define S_  1024
#define D_  1024
#define H_  16
#define HD_ 64
#define M_  (B_ * S_)     // 4096

// ---------------------------------------------------------------------------
// Scratch (device globals)
// ---------------------------------------------------------------------------
__device__ __align__(16) __half g_Xh   [(size_t)M_ * D_];        // x, k-permuted fp16
__device__ __align__(16) __half g_Wqkvh[(size_t)3 * D_ * D_];    // Wq|Wk|Wv
__device__ __align__(16) __half g_W1h  [(size_t)2 * D_ * D_];
__device__ __align__(16) __half g_W2h  [(size_t)2 * D_ * D_];
__device__ __align__(16) __half g_QKVh [(size_t)M_ * 3 * D_];    // Q,K permuted; V plain
__device__ __align__(16) __half g_Ch   [(size_t)M_ * D_];        // ctx, permuted fp16
__device__ __align__(16) __half g_Hh   [(size_t)M_ * 2 * D_];    // hidden, permuted fp16
__device__ __align__(16) float  g_bqkv [3 * D_];

// ---------------------------------------------------------------------------
// fp16 m16n8k16 MMA
__device__ __forceinline__ void mma_f16(float* c, const uint32_t* a, const uint32_t* b) {
    asm volatile(
        "mma.sync.aligned.m16n8k16.row.col.f32.f16.f16.f32 "
        "{%0,%1,%2,%3}, {%4,%5,%6,%7}, {%8,%9}, {%0,%1,%2,%3};\n"
        : "+f"(c[0]), "+f"(c[1]), "+f"(c[2]), "+f"(c[3])
        : "r"(a[0]), "r"(a[1]), "r"(a[2]), "r"(a[3]), "r"(b[0]), "r"(b[1]));
}

__device__ __forceinline__ void ldsm_x4_t(uint32_t& r0, uint32_t& r1,
                                          uint32_t& r2, uint32_t& r3, uint32_t addr) {
    asm volatile("ldmatrix.sync.aligned.m8n8.x4.trans.shared.b16 {%0,%1,%2,%3}, [%4];"
                 : "=r"(r0), "=r"(r1), "=r"(r2), "=r"(r3) : "r"(addr));
}

__device__ __forceinline__ uint32_t smem_u32(const void* p) {
    uint32_t a;
    asm("{ .reg .u64 t; cvta.to.shared.u64 t, %1; cvt.u32.u64 %0, t; }"
        : "=r"(a) : "l"(p));
    return a;
}

__device__ __forceinline__ void cp_async16(uint32_t dst, const void* src) {
    asm volatile("cp.async.cg.shared.global [%0], [%1], 16;"
                 :: "r"(dst), "l"(src) : "memory");
}

__device__ __forceinline__ uint32_t packh2(float x, float y) {
    __half2 h = __floats2half2_rn(x, y);
    return *(uint32_t*)&h;
}

// logical (even) n -> permuted phys position within its 16-group
__device__ __forceinline__ int permn(int n0) {
    return (n0 & ~15) | (((n0 >> 1) & 3) << 2) | ((n0 & 8) >> 2);
}

// ---------------------------------------------------------------------------
// Prep: fp32 -> k-permuted fp16, 16-element groups.
// phys halves [4q..4q+3] = logical {2q, 2q+1, 2q+8, 2q+9}
// ---------------------------------------------------------------------------
struct HSegs {
    const float* src[6];
    __half*      dst[6];
    int          cum[7];
};

__global__ void round_half_all(HSegs P) {
    const int i = blockIdx.x * blockDim.x + threadIdx.x;
    if (i >= P.cum[6]) return;
#pragma unroll
    for (int j = 0; j < 6; j++) {
        if (i < P.cum[j + 1]) {
            const int g = i - P.cum[j];
            const float4* s = (const float4*)P.src[j] + (size_t)g * 4;
            float l[16];
            *(float4*)&l[0]  = s[0];
            *(float4*)&l[4]  = s[1];
            *(float4*)&l[8]  = s[2];
            *(float4*)&l[12] = s[3];
            uint4 o0, o1;
            o0.x = packh2(l[0],  l[1]);  o0.y = packh2(l[8],  l[9]);
            o0.z = packh2(l[2],  l[3]);  o0.w = packh2(l[10], l[11]);
            o1.x = packh2(l[4],  l[5]);  o1.y = packh2(l[12], l[13]);
            o1.z = packh2(l[6],  l[7]);  o1.w = packh2(l[14], l[15]);
            uint4* d = (uint4*)(P.dst[j] + (size_t)g * 16);
            d[0] = o0; d[1] = o1;
            return;
        }
    }
}

__global__ void concat_bias(const float* __restrict__ a, const float* __restrict__ b,
                            const float* __restrict__ c, float* __restrict__ dst) {
    const int i = blockIdx.x * blockDim.x + threadIdx.x;
    if (i < 3 * D_)
        dst[i] = (i < D_) ? a[i] : ((i < 2 * D_) ? b[i - D_] : c[i - 2 * D_]);
}

// ---------------------------------------------------------------------------
// fp16 tensor-core GEMM: C[m,n] = sum_k A[m,k]*B[n,k] + bias[n]
// 128x128 tile, K-stage 32, 4-stage cp.async, warp tile 64x32.
// MODE: 0 = QKV (fp16 out: Q prescale+permute, K permute, V plain),
//       1 = MLP1 (ReLU, permuted-half out), 2 = MLP2 (plain fp32 out).
// ---------------------------------------------------------------------------
#define HROWB 96
#define HSTG_B (128 * HROWB)
#define HSTAGE_B (2 * HSTG_B)
#define HNST 4
#define HGEMM_SMEM (HNST * HSTAGE_B)  // 98,304

template <int MODE>
__global__ __launch_bounds__(256, 2)
void gemm_h(const __half* __restrict__ A, const __half* __restrict__ Bm,
            const float* __restrict__ bias, float* __restrict__ Cf,
            __half* __restrict__ Ch, int M, int N, int K)
{
    extern __shared__ __align__(16) char smc[];
    const uint32_t sb = smem_u32(smc);

    const int tid  = threadIdx.x;
    const int lane = tid & 31;
    const int wid  = tid >> 5;
    const int wm   = wid >> 2;
    const int wn   = wid & 3;
    const int grp  = lane >> 2;
    const int qid  = lane & 3;

    const int bm = blockIdx.y * 128;
    const int bn = blockIdx.x * 128;

    const __half* AgBase = A  + (size_t)bm * K;
    const __half* BgBase = Bm + (size_t)bn * K;

    auto issue_stage = [&](int stage, int buf) {
        const int k0 = stage * 32;
        const uint32_t sA = sb + (uint32_t)buf * HSTAGE_B;
        const uint32_t sB = sA + HSTG_B;
#pragma unroll
        for (int i = 0; i < 2; i++) {
            const int idx = tid + 256 * i;
            const int row = idx >> 2;
            const int c   = idx & 3;
            const uint32_t doff = (uint32_t)row * HROWB + (uint32_t)c * 16;
            cp_async16(sA + doff, AgBase + (size_t)row * K + k0 + c * 8);
            cp_async16(sB + doff, BgBase + (size_t)row * K + k0 + c * 8);
        }
        asm volatile("cp.async.commit_group;" ::: "memory");
    };

    float acc[4][4][4];
#pragma unroll
    for (int i = 0; i < 4; i++)
#pragma unroll
        for (int j = 0; j < 4; j++)
#pragma unroll
            for (int r = 0; r < 4; r++) acc[i][j][r] = 0.f;

    const int KT = K / 32;

    issue_stage(0, 0);
    issue_stage(1, 1);
    issue_stage(2, 2);

    for (int kt = 0; kt < KT; kt++) {
        const int buf = kt & (HNST - 1);

        if (kt < KT - 2)
            asm volatile("cp.async.wait_group 2;" ::: "memory");
        else if (kt == KT - 2)
            asm volatile("cp.async.wait_group 1;" ::: "memory");
        else
            asm volatile("cp.async.wait_group 0;" ::: "memory");
        __syncthreads();

        const char* Asb = smc + (size_t)buf * HSTAGE_B;
        const char* Bsb = Asb + HSTG_B;

#pragma unroll
        for (int s = 0; s < 2; s++) {
            uint32_t a[4][4];
#pragma unroll
            for (int mf = 0; mf < 4; mf++) {
                const int row = wm * 64 + mf * 16 + grp;
                const uint2 lo = *(const uint2*)(Asb + row * HROWB + s * 32 + qid * 8);
                const uint2 hi = *(const uint2*)(Asb + (row + 8) * HROWB + s * 32 + qid * 8);
                a[mf][0] = lo.x; a[mf][1] = hi.x; a[mf][2] = lo.y; a[mf][3] = hi.y;
            }
            uint32_t b[4][2];
#pragma unroll
            for (int nf = 0; nf < 4; nf++) {
                const int row = wn * 32 + nf * 8 + grp;
                const uint2 bv = *(const uint2*)(Bsb + row * HROWB + s * 32 + qid * 8);
                b[nf][0] = bv.x; b[nf][1] = bv.y;
            }
#pragma unroll
            for (int mf = 0; mf < 4; mf++)
#pragma unroll
                for (int nf = 0; nf < 4; nf++)
                    mma_f16(acc[mf][nf], a[mf], b[nf]);
        }

        if (kt + 3 < KT)
            issue_stage(kt + 3, (kt + 3) & (HNST - 1));
    }

    // ---- Epilogue ----
#pragma unroll
    for (int mf = 0; mf < 4; mf++) {
#pragma unroll
        for (int nf = 0; nf < 4; nf++) {
            const int m0 = bm + wm * 64 + mf * 16 + grp;
            const int n0 = bn + wn * 32 + nf * 8 + 2 * qid;
            const float bx = bias[n0], by = bias[n0 + 1];
            float2 v0, v1;
            v0.x = acc[mf][nf][0] + bx; v0.y = acc[mf][nf][1] + by;
            v1.x = acc[mf][nf][2] + bx; v1.y = acc[mf][nf][3] + by;

            if (MODE == 0) {
                // QKV: Q columns pre-scaled by 1/8; Q,K permuted fp16; V plain fp16
                if (n0 < D_) {
                    v0.x *= 0.125f; v0.y *= 0.125f;
                    v1.x *= 0.125f; v1.y *= 0.125f;
                }
                const int pn = (n0 < 2 * D_) ? permn(n0) : n0;
                *(uint32_t*)&Ch[(size_t)m0 * N + pn]       = packh2(v0.x, v0.y);
                *(uint32_t*)&Ch[(size_t)(m0 + 8) * N + pn] = packh2(v1.x, v1.y);
            } else if (MODE == 1) {
                v0.x = fmaxf(v0.x, 0.f); v0.y = fmaxf(v0.y, 0.f);
                v1.x = fmaxf(v1.x, 0.f); v1.y = fmaxf(v1.y, 0.f);
                const int pn = permn(n0);
                *(uint32_t*)&Ch[(size_t)m0 * N + pn]       = packh2(v0.x, v0.y);
                *(uint32_t*)&Ch[(size_t)(m0 + 8) * N + pn] = packh2(v1.x, v1.y);
            } else {
                *(float2*)&Cf[(size_t)m0 * N + n0]       = v0;
                *(float2*)&Cf[(size_t)(m0 + 8) * N + n0] = v1;
            }
        }
    }
}

// ---------------------------------------------------------------------------
// fp16 tensor-core flash attention.
// Q,K permuted fp16; V plain fp16 (transposed on the fly via ldmatrix.trans).
// P kept in registers (C-fragment -> A-fragment repack).
// ---------------------------------------------------------------------------
#define QT_ 128
#define QSTRB 160                       // 80 halves/row
#define KSTRB 160
#define VSTRB 144                       // 72 halves/row
#define QS_BYTES   (QT_ * QSTRB)        // 20,480
#define KSTG_BYTES (64 * KSTRB)         // 10,240
#define VSTG_BYTES (64 * VSTRB)         //  9,216
#define ATTN_SMEM_BYTES (QS_BYTES + 2 * KSTG_BYTES + 2 * VSTG_BYTES)  // 59,392

__global__ __launch_bounds__(256, 2)
void attn_h(const __half* __restrict__ QKV, const int* __restrict__ mask,
            __half* __restrict__ O)
{
    extern __shared__ __align__(16) char smb[];
    const uint32_t sb  = smem_u32(smb);
    const uint32_t sQ  = sb;
    const uint32_t sK  = sb + QS_BYTES;
    const uint32_t sV  = sK + 2 * KSTG_BYTES;
    const char* Qsp = smb;
    const char* Ksp = smb + QS_BYTES;
    const char* Vsp = Ksp + 2 * KSTG_BYTES;

    const int tid  = threadIdx.x;
    const int lane = tid & 31;
    const int wid  = tid >> 5;
    const int grp  = lane >> 2;
    const int qid  = lane & 3;

    const int qt = blockIdx.x;
    const int bh = blockIdx.y;
    const int b  = bh >> 4;
    const int h  = bh & 15;
    const int q0 = qt * QT_;

    const int LDQ = 3 * D_;
    const __half* Qb = QKV + (size_t)b * S_ * LDQ + (size_t)h * HD_;
    const __half* Kb = Qb + D_;
    const __half* Vb = Qb + 2 * D_;

    auto issue_kv = [&](int kt, int buf) {
        const int k0g = kt * 64;
#pragma unroll
        for (int i = 0; i < 2; i++) {
            const int idx = tid + 256 * i;       // 0..511
            const int row = idx >> 3;            // 0..63
            const int ch  = idx & 7;             // 8 chunks of 16B = 64 halves
            cp_async16(sK + (uint32_t)buf * KSTG_BYTES + (uint32_t)row * KSTRB + ch * 16,
                       Kb + (size_t)(k0g + row) * LDQ + ch * 8);
            cp_async16(sV + (uint32_t)buf * VSTG_BYTES + (uint32_t)row * VSTRB + ch * 16,
                       Vb + (size_t)(k0g + row) * LDQ + ch * 8);
        }
        asm volatile("cp.async.commit_group;" ::: "memory");
    };

    issue_kv(0, 0);

    // Q tile (permuted fp16, pre-scaled): 128 rows x 64 halves
#pragma unroll
    for (int i = 0; i < 4; i++) {
        const int idx = tid + 256 * i;           // 0..1023
        const int row = idx >> 3;
        const int ch  = idx & 7;
        cp_async16(sQ + (uint32_t)row * QSTRB + ch * 16,
                   Qb + (size_t)(q0 + row) * LDQ + ch * 8);
    }
    asm volatile("cp.async.commit_group;" ::: "memory");

    const int qrow0 = wid * 16 + grp;
    const int* mrow0 = mask + (size_t)(b * S_ + q0 + qrow0) * S_;
    const int* mrow1 = mrow0 + 8 * S_;

    float mi0 = -1e30f, mi1 = -1e30f, li0 = 0.f, li1 = 0.f;
    float o[8][4];
#pragma unroll
    for (int nf = 0; nf < 8; nf++)
#pragma unroll
        for (int r = 0; r < 4; r++) o[nf][r] = 0.f;

    for (int kt = 0; kt < S_ / 64; kt++) {
        const int buf = kt & 1;
        const int k0  = kt * 64;

        asm volatile("cp.async.wait_group 0;" ::: "memory");
        __syncthreads();

        if (kt + 1 < S_ / 64)
            issue_kv(kt + 1, buf ^ 1);

        const char* Kb2 = Ksp + (size_t)buf * KSTG_BYTES;
        const uint32_t Vb2 = sV + (uint32_t)buf * VSTG_BYTES;

        // ---- QK^T (fp16 m16n8k16, 4 k-steps over d=64) ----
        float c[8][4];
#pragma unroll
        for (int nf = 0; nf < 8; nf++)
#pragma unroll
            for (int r = 0; r < 4; r++) c[nf][r] = 0.f;

#pragma unroll
        for (int s = 0; s < 4; s++) {
            const uint2 lo = *(const uint2*)(Qsp + qrow0 * QSTRB + s * 32 + qid * 8);
            const uint2 hi = *(const uint2*)(Qsp + (qrow0 + 8) * QSTRB + s * 32 + qid * 8);
            uint32_t a[4] = { lo.x, hi.x, lo.y, hi.y };
#pragma unroll
            for (int nf = 0; nf < 8; nf++) {
                const uint2 bv = *(const uint2*)(Kb2 + (nf * 8 + grp) * KSTRB + s * 32 + qid * 8);
                uint32_t bb[2] = { bv.x, bv.y };
                mma_f16(c[nf], a, bb);
            }
        }

        // ---- mask ----
#pragma unroll
        for (int nf = 0; nf < 8; nf++) {
            const int kc = k0 + nf * 8 + 2 * qid;
            const int2 m0 = *(const int2*)&mrow0[kc];
            const int2 m1 = *(const int2*)&mrow1[kc];
            if (m0.x == 0) c[nf][0] = -1e8f;
            if (m0.y == 0) c[nf][1] = -1e8f;
            if (m1.x == 0) c[nf][2] = -1e8f;
            if (m1.y == 0) c[nf][3] = -1e8f;
        }

        // ---- online softmax on fragments ----
        float mx0 = -1e30f, mx1 = -1e30f;
#pragma unroll
        for (int nf = 0; nf < 8; nf++) {
            mx0 = fmaxf(mx0, fmaxf(c[nf][0], c[nf][1]));
            mx1 = fmaxf(mx1, fmaxf(c[nf][2], c[nf][3]));
        }
        mx0 = fmaxf(mx0, __shfl_xor_sync(0xffffffffu, mx0, 1));
        mx0 = fmaxf(mx0, __shfl_xor_sync(0xffffffffu, mx0, 2));
        mx1 = fmaxf(mx1, __shfl_xor_sync(0xffffffffu, mx1, 1));
        mx1 = fmaxf(mx1, __shfl_xor_sync(0xffffffffu, mx1, 2));

        const float mn0 = fmaxf(mi0, mx0);
        const float mn1 = fmaxf(mi1, mx1);
        const float al0 = __expf(mi0 - mn0);
        const float al1 = __expf(mi1 - mn1);

        float sum0 = 0.f, sum1 = 0.f;
#pragma unroll
        for (int nf = 0; nf < 8; nf++) {
            float e;
            e = __expf(c[nf][0] - mn0); sum0 += e; c[nf][0] = e;
            e = __expf(c[nf][1] - mn0); sum0 += e; c[nf][1] = e;
            e = __expf(c[nf][2] - mn1); sum1 += e; c[nf][2] = e;
            e = __expf(c[nf][3] - mn1); sum1 += e; c[nf][3] = e;
        }
        sum0 += __shfl_xor_sync(0xffffffffu, sum0, 1);
        sum0 += __shfl_xor_sync(0xffffffffu, sum0, 2);
        sum1 += __shfl_xor_sync(0xffffffffu, sum1, 1);
        sum1 += __shfl_xor_sync(0xffffffffu, sum1, 2);

        li0 = li0 * al0 + sum0;  mi0 = mn0;
        li1 = li1 * al1 + sum1;  mi1 = mn1;

#pragma unroll
        for (int nf = 0; nf < 8; nf++) {
            o[nf][0] *= al0; o[nf][1] *= al0;
            o[nf][2] *= al1; o[nf][3] *= al1;
        }

        // ---- PV: A = P (in-register repack), B = V via ldmatrix.trans ----
        const int lmi = lane >> 3;       // matrix index 0..3
        const int lmr = lane & 7;        // row within matrix
#pragma unroll
        for (int s = 0; s < 4; s++) {
            uint32_t a[4];
            a[0] = packh2(c[2 * s][0],     c[2 * s][1]);
            a[1] = packh2(c[2 * s][2],     c[2 * s][3]);
            a[2] = packh2(c[2 * s + 1][0], c[2 * s + 1][1]);
            a[3] = packh2(c[2 * s + 1][2], c[2 * s + 1][3]);
#pragma unroll
            for (int nfp = 0; nfp < 4; nfp++) {
                const int vrow = 16 * s + ((lmi & 1) << 3) + lmr;
                const int vcol = 16 * nfp + ((lmi >> 1) << 3);
                uint32_t b0, b1, b2, b3;
                ldsm_x4_t(b0, b1, b2, b3,
                          Vb2 + (uint32_t)vrow * VSTRB + (uint32_t)vcol * 2);
                { uint32_t bb[2] = { b0, b1 }; mma_f16(o[2 * nfp],     a, bb); }
                { uint32_t bb[2] = { b2, b3 }; mma_f16(o[2 * nfp + 1], a, bb); }
            }
        }
    }

    // ---- finalize: ctx as permuted fp16 (consumed by fp16 MLP1) ----
    const float inv0 = 1.0f / li0;
    const float inv1 = 1.0f / li1;
    __half* row0g = O + (size_t)(b * S_ + q0 + qrow0) * D_ + (size_t)h * HD_;
    __half* row1g = row0g + (size_t)8 * D_;
#pragma unroll
    for (int nf = 0; nf < 8; nf++) {
        const int d0 = nf * 8 + 2 * qid;
        const int pd = (d0 & 48) | (((d0 >> 1) & 3) << 2) | ((d0 & 8) >> 2);
        *(uint32_t*)(row0g + pd) = packh2(o[nf][0] * inv0, o[nf][1] * inv0);
        *(uint32_t*)(row1g + pd) = packh2(o[nf][2] * inv1, o[nf][3] * inv1);
    }
}

// ---------------------------------------------------------------------------
// Launch.  Inputs: x, Wq, bq, Wk, bk, Wv, bv, W1, b1, W2, b2, mask
// ---------------------------------------------------------------------------
extern "C" void kernel_launch(void* const* d_in, const int* in_sizes, int n_in,
                              void* d_out, int out_size)
{
    const float* x    = (const float*)d_in[0];
    const float* Wq   = (const float*)d_in[1];
    const float* bq   = (const float*)d_in[2];
    const float* Wk   = (const float*)d_in[3];
    const float* bk   = (const float*)d_in[4];
    const float* Wv   = (const float*)d_in[5];
    const float* bv   = (const float*)d_in[6];
    const float* W1   = (const float*)d_in[7];
    const float* b1   = (const float*)d_in[8];
    const float* W2   = (const float*)d_in[9];
    const float* b2   = (const float*)d_in[10];
    const int*   mask = (const int*)d_in[11];
    float*       out  = (float*)d_out;

    __half *Xh, *Wqkvh, *W1h, *W2h, *QKVh, *Chp, *Hhp;
    float *bqkvp;
    cudaGetSymbolAddress((void**)&Xh,    g_Xh);
    cudaGetSymbolAddress((void**)&Wqkvh, g_Wqkvh);
    cudaGetSymbolAddress((void**)&W1h,   g_W1h);
    cudaGetSymbolAddress((void**)&W2h,   g_W2h);
    cudaGetSymbolAddress((void**)&QKVh,  g_QKVh);
    cudaGetSymbolAddress((void**)&Chp,   g_Ch);
    cudaGetSymbolAddress((void**)&Hhp,   g_Hh);
    cudaGetSymbolAddress((void**)&bqkvp, g_bqkv);

    cudaFuncSetAttribute(attn_h,
                         cudaFuncAttributeMaxDynamicSharedMemorySize, ATTN_SMEM_BYTES);
    cudaFuncSetAttribute((const void*)gemm_h<0>,
                         cudaFuncAttributeMaxDynamicSharedMemorySize, HGEMM_SMEM);
    cudaFuncSetAttribute((const void*)gemm_h<1>,
                         cudaFuncAttributeMaxDynamicSharedMemorySize, HGEMM_SMEM);
    cudaFuncSetAttribute((const void*)gemm_h<2>,
                         cudaFuncAttributeMaxDynamicSharedMemorySize, HGEMM_SMEM);

    const dim3 blk(256);
    const int T = 256;

    // ---- prep: fp32 -> permuted fp16 for x and all weights ----
    HSegs P;
    P.src[0] = x;  P.dst[0] = Xh;
    P.src[1] = Wq; P.dst[1] = Wqkvh;
    P.src[2] = Wk; P.dst[2] = Wqkvh + (size_t)D_ * D_;
    P.src[3] = Wv; P.dst[3] = Wqkvh + (size_t)2 * D_ * D_;
    P.src[4] = W1; P.dst[4] = W1h;
    P.src[5] = W2; P.dst[5] = W2h;
    const int gr[6] = { M_ * D_ / 16, D_ * D_ / 16, D_ * D_ / 16, D_ * D_ / 16,
                        2 * D_ * D_ / 16, 2 * D_ * D_ / 16 };
    P.cum[0] = 0;
    for (int j = 0; j < 6; j++) P.cum[j + 1] = P.cum[j] + gr[j];
    round_half_all<<<(P.cum[6] + T - 1) / T, T>>>(P);
    concat_bias<<<(3 * D_ + T - 1) / T, T>>>(bq, bk, bv, bqkvp);

    // ---- fused QKV projection (fp16 out: Q prescale+perm, K perm, V plain) --
    gemm_h<0><<<dim3(3 * D_ / 128, M_ / 128), blk, HGEMM_SMEM>>>(
        Xh, Wqkvh, bqkvp, (float*)nullptr, QKVh, M_, 3 * D_, D_);

    // ---- attention (fp16; ctx out as permuted fp16) ----
    attn_h<<<dim3(S_ / QT_, B_ * H_), blk, ATTN_SMEM_BYTES>>>(QKVh, mask, Chp);

    // ---- MLP ----
    gemm_h<1><<<dim3(2 * D_ / 128, M_ / 128), blk, HGEMM_SMEM>>>(
        Chp, W1h, b1, (float*)nullptr, Hhp, M_, 2 * D_, D_);
    gemm_h<2><<<dim3(D_ / 128, M_ / 128), blk, HGEMM_SMEM>>>(
        Hhp, W2h, b2, out, (__half*)nullptr, M_, D_, 2 * D_);
}

// round 11
// speedup vs baseline: 5.9328x; 1.0712x over previous
#include <cuda_runtime.h>
#include <cuda_fp16.h>
#include <stdint.h>

#define B_  4
#define S_  1024
#define D_  1024
#define H_  16
#define HD_ 64
#define M_  (B_ * S_)     // 4096

// ---------------------------------------------------------------------------
// Scratch (device globals)
// ---------------------------------------------------------------------------
__device__ __align__(16) __half g_Xh   [(size_t)M_ * D_];        // x, k-permuted fp16
__device__ __align__(16) __half g_Wqkvh[(size_t)3 * D_ * D_];    // Wq|Wk|Wv
__device__ __align__(16) __half g_W1h  [(size_t)2 * D_ * D_];
__device__ __align__(16) __half g_W2h  [(size_t)2 * D_ * D_];
__device__ __align__(16) __half g_QKVh [(size_t)M_ * 3 * D_];    // Q,K permuted; V plain
__device__ __align__(16) __half g_Ch   [(size_t)M_ * D_];        // ctx, permuted fp16
__device__ __align__(16) __half g_Hh   [(size_t)M_ * 2 * D_];    // hidden, permuted fp16
__device__ __align__(16) float  g_bqkv [3 * D_];
__device__ int g_mflag[B_ * (S_ / 128) * (S_ / 64)];             // 512 dirty flags

// ---------------------------------------------------------------------------
// fp16 m16n8k16 MMA
__device__ __forceinline__ void mma_f16(float* c, const uint32_t* a, const uint32_t* b) {
    asm volatile(
        "mma.sync.aligned.m16n8k16.row.col.f32.f16.f16.f32 "
        "{%0,%1,%2,%3}, {%4,%5,%6,%7}, {%8,%9}, {%0,%1,%2,%3};\n"
        : "+f"(c[0]), "+f"(c[1]), "+f"(c[2]), "+f"(c[3])
        : "r"(a[0]), "r"(a[1]), "r"(a[2]), "r"(a[3]), "r"(b[0]), "r"(b[1]));
}

__device__ __forceinline__ void ldsm_x4_t(uint32_t& r0, uint32_t& r1,
                                          uint32_t& r2, uint32_t& r3, uint32_t addr) {
    asm volatile("ldmatrix.sync.aligned.m8n8.x4.trans.shared.b16 {%0,%1,%2,%3}, [%4];"
                 : "=r"(r0), "=r"(r1), "=r"(r2), "=r"(r3) : "r"(addr));
}

__device__ __forceinline__ uint32_t smem_u32(const void* p) {
    uint32_t a;
    asm("{ .reg .u64 t; cvta.to.shared.u64 t, %1; cvt.u32.u64 %0, t; }"
        : "=r"(a) : "l"(p));
    return a;
}

__device__ __forceinline__ void cp_async16(uint32_t dst, const void* src) {
    asm volatile("cp.async.cg.shared.global [%0], [%1], 16;"
                 :: "r"(dst), "l"(src) : "memory");
}

__device__ __forceinline__ uint32_t packh2(float x, float y) {
    __half2 h = __floats2half2_rn(x, y);
    return *(uint32_t*)&h;
}

// logical (even) n -> permuted phys position within its 16-group
__device__ __forceinline__ int permn(int n0) {
    return (n0 & ~15) | (((n0 >> 1) & 3) << 2) | ((n0 & 8) >> 2);
}

// ---------------------------------------------------------------------------
// Prep: fp32 -> k-permuted fp16, 16-element groups.
// ---------------------------------------------------------------------------
struct HSegs {
    const float* src[6];
    __half*      dst[6];
    int          cum[7];
};

__global__ void round_half_all(HSegs P) {
    const int i = blockIdx.x * blockDim.x + threadIdx.x;
    if (i >= P.cum[6]) return;
#pragma unroll
    for (int j = 0; j < 6; j++) {
        if (i < P.cum[j + 1]) {
            const int g = i - P.cum[j];
            const float4* s = (const float4*)P.src[j] + (size_t)g * 4;
            float l[16];
            *(float4*)&l[0]  = s[0];
            *(float4*)&l[4]  = s[1];
            *(float4*)&l[8]  = s[2];
            *(float4*)&l[12] = s[3];
            uint4 o0, o1;
            o0.x = packh2(l[0],  l[1]);  o0.y = packh2(l[8],  l[9]);
            o0.z = packh2(l[2],  l[3]);  o0.w = packh2(l[10], l[11]);
            o1.x = packh2(l[4],  l[5]);  o1.y = packh2(l[12], l[13]);
            o1.z = packh2(l[6],  l[7]);  o1.w = packh2(l[14], l[15]);
            uint4* d = (uint4*)(P.dst[j] + (size_t)g * 16);
            d[0] = o0; d[1] = o1;
            return;
        }
    }
}

__global__ void concat_bias(const float* __restrict__ a, const float* __restrict__ b,
                            const float* __restrict__ c, float* __restrict__ dst) {
    const int i = blockIdx.x * blockDim.x + threadIdx.x;
    if (i < 3 * D_)
        dst[i] = (i < D_) ? a[i] : ((i < 2 * D_) ? b[i - D_] : c[i - 2 * D_]);
}

// Scan mask: one block per (b, qtile[128], ktile[64]) region; flag = any zero.
__global__ __launch_bounds__(256)
void mask_scan(const int* __restrict__ mask, int* __restrict__ flags) {
    const int fidx = blockIdx.x;
    const int kt = fidx & 15;            // 16 k-tiles
    const int qt = (fidx >> 4) & 7;      // 8 q-tiles
    const int b  = fidx >> 7;            // 4 batches
    const int q0 = qt * 128;
    const int k0 = kt * 64;
    const int tid = threadIdx.x;

    int ok = 1;
    // 128 rows x 64 cols = 8192 ints; 256 threads x 8 int4 each
#pragma unroll
    for (int i = 0; i < 8; i++) {
        const int idx = tid + 256 * i;       // 0..2047 int4 slots
        const int row = idx >> 4;            // 0..127
        const int c4  = (idx & 15) * 4;      // 0..60
        const int4 v = *(const int4*)&mask[((size_t)(b * S_ + q0 + row)) * S_ + k0 + c4];
        if ((v.x & v.y & v.z & v.w) == 0)    // any component zero? (mask is 0/1)
            if (v.x == 0 || v.y == 0 || v.z == 0 || v.w == 0) ok = 0;
    }
    const int all_ok = __syncthreads_and(ok);
    if (tid == 0) flags[fidx] = !all_ok;
}

// ---------------------------------------------------------------------------
// fp16 tensor-core GEMM (unchanged from R10)
// ---------------------------------------------------------------------------
#define HROWB 96
#define HSTG_B (128 * HROWB)
#define HSTAGE_B (2 * HSTG_B)
#define HNST 4
#define HGEMM_SMEM (HNST * HSTAGE_B)  // 98,304

template <int MODE>
__global__ __launch_bounds__(256, 2)
void gemm_h(const __half* __restrict__ A, const __half* __restrict__ Bm,
            const float* __restrict__ bias, float* __restrict__ Cf,
            __half* __restrict__ Ch, int M, int N, int K)
{
    extern __shared__ __align__(16) char smc[];
    const uint32_t sb = smem_u32(smc);

    const int tid  = threadIdx.x;
    const int lane = tid & 31;
    const int wid  = tid >> 5;
    const int wm   = wid >> 2;
    const int wn   = wid & 3;
    const int grp  = lane >> 2;
    const int qid  = lane & 3;

    const int bm = blockIdx.y * 128;
    const int bn = blockIdx.x * 128;

    const __half* AgBase = A  + (size_t)bm * K;
    const __half* BgBase = Bm + (size_t)bn * K;

    auto issue_stage = [&](int stage, int buf) {
        const int k0 = stage * 32;
        const uint32_t sA = sb + (uint32_t)buf * HSTAGE_B;
        const uint32_t sB = sA + HSTG_B;
#pragma unroll
        for (int i = 0; i < 2; i++) {
            const int idx = tid + 256 * i;
            const int row = idx >> 2;
            const int c   = idx & 3;
            const uint32_t doff = (uint32_t)row * HROWB + (uint32_t)c * 16;
            cp_async16(sA + doff, AgBase + (size_t)row * K + k0 + c * 8);
            cp_async16(sB + doff, BgBase + (size_t)row * K + k0 + c * 8);
        }
        asm volatile("cp.async.commit_group;" ::: "memory");
    };

    float acc[4][4][4];
#pragma unroll
    for (int i = 0; i < 4; i++)
#pragma unroll
        for (int j = 0; j < 4; j++)
#pragma unroll
            for (int r = 0; r < 4; r++) acc[i][j][r] = 0.f;

    const int KT = K / 32;

    issue_stage(0, 0);
    issue_stage(1, 1);
    issue_stage(2, 2);

    for (int kt = 0; kt < KT; kt++) {
        const int buf = kt & (HNST - 1);

        if (kt < KT - 2)
            asm volatile("cp.async.wait_group 2;" ::: "memory");
        else if (kt == KT - 2)
            asm volatile("cp.async.wait_group 1;" ::: "memory");
        else
            asm volatile("cp.async.wait_group 0;" ::: "memory");
        __syncthreads();

        const char* Asb = smc + (size_t)buf * HSTAGE_B;
        const char* Bsb = Asb + HSTG_B;

#pragma unroll
        for (int s = 0; s < 2; s++) {
            uint32_t a[4][4];
#pragma unroll
            for (int mf = 0; mf < 4; mf++) {
                const int row = wm * 64 + mf * 16 + grp;
                const uint2 lo = *(const uint2*)(Asb + row * HROWB + s * 32 + qid * 8);
                const uint2 hi = *(const uint2*)(Asb + (row + 8) * HROWB + s * 32 + qid * 8);
                a[mf][0] = lo.x; a[mf][1] = hi.x; a[mf][2] = lo.y; a[mf][3] = hi.y;
            }
            uint32_t b[4][2];
#pragma unroll
            for (int nf = 0; nf < 4; nf++) {
                const int row = wn * 32 + nf * 8 + grp;
                const uint2 bv = *(const uint2*)(Bsb + row * HROWB + s * 32 + qid * 8);
                b[nf][0] = bv.x; b[nf][1] = bv.y;
            }
#pragma unroll
            for (int mf = 0; mf < 4; mf++)
#pragma unroll
                for (int nf = 0; nf < 4; nf++)
                    mma_f16(acc[mf][nf], a[mf], b[nf]);
        }

        if (kt + 3 < KT)
            issue_stage(kt + 3, (kt + 3) & (HNST - 1));
    }

#pragma unroll
    for (int mf = 0; mf < 4; mf++) {
#pragma unroll
        for (int nf = 0; nf < 4; nf++) {
            const int m0 = bm + wm * 64 + mf * 16 + grp;
            const int n0 = bn + wn * 32 + nf * 8 + 2 * qid;
            const float bx = bias[n0], by = bias[n0 + 1];
            float2 v0, v1;
            v0.x = acc[mf][nf][0] + bx; v0.y = acc[mf][nf][1] + by;
            v1.x = acc[mf][nf][2] + bx; v1.y = acc[mf][nf][3] + by;

            if (MODE == 0) {
                if (n0 < D_) {
                    v0.x *= 0.125f; v0.y *= 0.125f;
                    v1.x *= 0.125f; v1.y *= 0.125f;
                }
                const int pn = (n0 < 2 * D_) ? permn(n0) : n0;
                *(uint32_t*)&Ch[(size_t)m0 * N + pn]       = packh2(v0.x, v0.y);
                *(uint32_t*)&Ch[(size_t)(m0 + 8) * N + pn] = packh2(v1.x, v1.y);
            } else if (MODE == 1) {
                v0.x = fmaxf(v0.x, 0.f); v0.y = fmaxf(v0.y, 0.f);
                v1.x = fmaxf(v1.x, 0.f); v1.y = fmaxf(v1.y, 0.f);
                const int pn = permn(n0);
                *(uint32_t*)&Ch[(size_t)m0 * N + pn]       = packh2(v0.x, v0.y);
                *(uint32_t*)&Ch[(size_t)(m0 + 8) * N + pn] = packh2(v1.x, v1.y);
            } else {
                *(float2*)&Cf[(size_t)m0 * N + n0]       = v0;
                *(float2*)&Cf[(size_t)(m0 + 8) * N + n0] = v1;
            }
        }
    }
}

// ---------------------------------------------------------------------------
// fp16 tensor-core flash attention + per-tile mask dirty flags.
// ---------------------------------------------------------------------------
#define QT_ 128
#define QSTRB 160
#define KSTRB 160
#define VSTRB 144
#define QS_BYTES   (QT_ * QSTRB)
#define KSTG_BYTES (64 * KSTRB)
#define VSTG_BYTES (64 * VSTRB)
#define ATTN_SMEM_BYTES (QS_BYTES + 2 * KSTG_BYTES + 2 * VSTG_BYTES)  // 59,392

__global__ __launch_bounds__(256, 2)
void attn_h(const __half* __restrict__ QKV, const int* __restrict__ mask,
            const int* __restrict__ mflag, __half* __restrict__ O)
{
    extern __shared__ __align__(16) char smb[];
    const uint32_t sb  = smem_u32(smb);
    const uint32_t sQ  = sb;
    const uint32_t sK  = sb + QS_BYTES;
    const uint32_t sV  = sK + 2 * KSTG_BYTES;
    const char* Qsp = smb;
    const char* Ksp = smb + QS_BYTES;

    const int tid  = threadIdx.x;
    const int lane = tid & 31;
    const int wid  = tid >> 5;
    const int grp  = lane >> 2;
    const int qid  = lane & 3;

    const int qt = blockIdx.x;
    const int bh = blockIdx.y;
    const int b  = bh >> 4;
    const int h  = bh & 15;
    const int q0 = qt * QT_;

    const int LDQ = 3 * D_;
    const __half* Qb = QKV + (size_t)b * S_ * LDQ + (size_t)h * HD_;
    const __half* Kb = Qb + D_;
    const __half* Vb = Qb + 2 * D_;
    const int* mfbase = mflag + (b * (S_ / QT_) + qt) * (S_ / 64);

    auto issue_kv = [&](int kt, int buf) {
        const int k0g = kt * 64;
#pragma unroll
        for (int i = 0; i < 2; i++) {
            const int idx = tid + 256 * i;
            const int row = idx >> 3;
            const int ch  = idx & 7;
            cp_async16(sK + (uint32_t)buf * KSTG_BYTES + (uint32_t)row * KSTRB + ch * 16,
                       Kb + (size_t)(k0g + row) * LDQ + ch * 8);
            cp_async16(sV + (uint32_t)buf * VSTG_BYTES + (uint32_t)row * VSTRB + ch * 16,
                       Vb + (size_t)(k0g + row) * LDQ + ch * 8);
        }
        asm volatile("cp.async.commit_group;" ::: "memory");
    };

    issue_kv(0, 0);

#pragma unroll
    for (int i = 0; i < 4; i++) {
        const int idx = tid + 256 * i;
        const int row = idx >> 3;
        const int ch  = idx & 7;
        cp_async16(sQ + (uint32_t)row * QSTRB + ch * 16,
                   Qb + (size_t)(q0 + row) * LDQ + ch * 8);
    }
    asm volatile("cp.async.commit_group;" ::: "memory");

    const int qrow0 = wid * 16 + grp;
    const int* mrow0 = mask + (size_t)(b * S_ + q0 + qrow0) * S_;
    const int* mrow1 = mrow0 + 8 * S_;

    float mi0 = -1e30f, mi1 = -1e30f, li0 = 0.f, li1 = 0.f;
    float o[8][4];
#pragma unroll
    for (int nf = 0; nf < 8; nf++)
#pragma unroll
        for (int r = 0; r < 4; r++) o[nf][r] = 0.f;

    for (int kt = 0; kt < S_ / 64; kt++) {
        const int buf = kt & 1;
        const int k0  = kt * 64;
        const bool dirty = mfbase[kt] != 0;

        asm volatile("cp.async.wait_group 0;" ::: "memory");
        __syncthreads();

        if (kt + 1 < S_ / 64)
            issue_kv(kt + 1, buf ^ 1);

        const char* Kb2 = Ksp + (size_t)buf * KSTG_BYTES;
        const uint32_t Vb2 = sV + (uint32_t)buf * VSTG_BYTES;

        // ---- QK^T ----
        float c[8][4];
#pragma unroll
        for (int nf = 0; nf < 8; nf++)
#pragma unroll
            for (int r = 0; r < 4; r++) c[nf][r] = 0.f;

#pragma unroll
        for (int s = 0; s < 4; s++) {
            const uint2 lo = *(const uint2*)(Qsp + qrow0 * QSTRB + s * 32 + qid * 8);
            const uint2 hi = *(const uint2*)(Qsp + (qrow0 + 8) * QSTRB + s * 32 + qid * 8);
            uint32_t a[4] = { lo.x, hi.x, lo.y, hi.y };
#pragma unroll
            for (int nf = 0; nf < 8; nf++) {
                const uint2 bv = *(const uint2*)(Kb2 + (nf * 8 + grp) * KSTRB + s * 32 + qid * 8);
                uint32_t bb[2] = { bv.x, bv.y };
                mma_f16(c[nf], a, bb);
            }
        }

        // ---- mask (only when this tile has zeros) ----
        if (dirty) {
#pragma unroll
            for (int nf = 0; nf < 8; nf++) {
                const int kc = k0 + nf * 8 + 2 * qid;
                const int2 m0 = *(const int2*)&mrow0[kc];
                const int2 m1 = *(const int2*)&mrow1[kc];
                if (m0.x == 0) c[nf][0] = -1e8f;
                if (m0.y == 0) c[nf][1] = -1e8f;
                if (m1.x == 0) c[nf][2] = -1e8f;
                if (m1.y == 0) c[nf][3] = -1e8f;
            }
        }

        // ---- online softmax on fragments ----
        float mx0 = -1e30f, mx1 = -1e30f;
#pragma unroll
        for (int nf = 0; nf < 8; nf++) {
            mx0 = fmaxf(mx0, fmaxf(c[nf][0], c[nf][1]));
            mx1 = fmaxf(mx1, fmaxf(c[nf][2], c[nf][3]));
        }
        mx0 = fmaxf(mx0, __shfl_xor_sync(0xffffffffu, mx0, 1));
        mx0 = fmaxf(mx0, __shfl_xor_sync(0xffffffffu, mx0, 2));
        mx1 = fmaxf(mx1, __shfl_xor_sync(0xffffffffu, mx1, 1));
        mx1 = fmaxf(mx1, __shfl_xor_sync(0xffffffffu, mx1, 2));

        const float mn0 = fmaxf(mi0, mx0);
        const float mn1 = fmaxf(mi1, mx1);
        const float al0 = __expf(mi0 - mn0);
        const float al1 = __expf(mi1 - mn1);

        float sum0 = 0.f, sum1 = 0.f;
#pragma unroll
        for (int nf = 0; nf < 8; nf++) {
            float e;
            e = __expf(c[nf][0] - mn0); sum0 += e; c[nf][0] = e;
            e = __expf(c[nf][1] - mn0); sum0 += e; c[nf][1] = e;
            e = __expf(c[nf][2] - mn1); sum1 += e; c[nf][2] = e;
            e = __expf(c[nf][3] - mn1); sum1 += e; c[nf][3] = e;
        }
        sum0 += __shfl_xor_sync(0xffffffffu, sum0, 1);
        sum0 += __shfl_xor_sync(0xffffffffu, sum0, 2);
        sum1 += __shfl_xor_sync(0xffffffffu, sum1, 1);
        sum1 += __shfl_xor_sync(0xffffffffu, sum1, 2);

        li0 = li0 * al0 + sum0;  mi0 = mn0;
        li1 = li1 * al1 + sum1;  mi1 = mn1;

#pragma unroll
        for (int nf = 0; nf < 8; nf++) {
            o[nf][0] *= al0; o[nf][1] *= al0;
            o[nf][2] *= al1; o[nf][3] *= al1;
        }

        // ---- PV ----
        const int lmi = lane >> 3;
        const int lmr = lane & 7;
#pragma unroll
        for (int s = 0; s < 4; s++) {
            uint32_t a[4];
            a[0] = packh2(c[2 * s][0],     c[2 * s][1]);
            a[1] = packh2(c[2 * s][2],     c[2 * s][3]);
            a[2] = packh2(c[2 * s + 1][0], c[2 * s + 1][1]);
            a[3] = packh2(c[2 * s + 1][2], c[2 * s + 1][3]);
#pragma unroll
            for (int nfp = 0; nfp < 4; nfp++) {
                const int vrow = 16 * s + ((lmi & 1) << 3) + lmr;
                const int vcol = 16 * nfp + ((lmi >> 1) << 3);
                uint32_t b0, b1, b2, b3;
                ldsm_x4_t(b0, b1, b2, b3,
                          Vb2 + (uint32_t)vrow * VSTRB + (uint32_t)vcol * 2);
                { uint32_t bb[2] = { b0, b1 }; mma_f16(o[2 * nfp],     a, bb); }
                { uint32_t bb[2] = { b2, b3 }; mma_f16(o[2 * nfp + 1], a, bb); }
            }
        }
    }

    // ---- finalize: ctx as permuted fp16 ----
    const float inv0 = 1.0f / li0;
    const float inv1 = 1.0f / li1;
    __half* row0g = O + (size_t)(b * S_ + q0 + qrow0) * D_ + (size_t)h * HD_;
    __half* row1g = row0g + (size_t)8 * D_;
#pragma unroll
    for (int nf = 0; nf < 8; nf++) {
        const int d0 = nf * 8 + 2 * qid;
        const int pd = (d0 & 48) | (((d0 >> 1) & 3) << 2) | ((d0 & 8) >> 2);
        *(uint32_t*)(row0g + pd) = packh2(o[nf][0] * inv0, o[nf][1] * inv0);
        *(uint32_t*)(row1g + pd) = packh2(o[nf][2] * inv1, o[nf][3] * inv1);
    }
}

// ---------------------------------------------------------------------------
// Launch.  Inputs: x, Wq, bq, Wk, bk, Wv, bv, W1, b1, W2, b2, mask
// ---------------------------------------------------------------------------
extern "C" void kernel_launch(void* const* d_in, const int* in_sizes, int n_in,
                              void* d_out, int out_size)
{
    const float* x    = (const float*)d_in[0];
    const float* Wq   = (const float*)d_in[1];
    const float* bq   = (const float*)d_in[2];
    const float* Wk   = (const float*)d_in[3];
    const float* bk   = (const float*)d_in[4];
    const float* Wv   = (const float*)d_in[5];
    const float* bv   = (const float*)d_in[6];
    const float* W1   = (const float*)d_in[7];
    const float* b1   = (const float*)d_in[8];
    const float* W2   = (const float*)d_in[9];
    const float* b2   = (const float*)d_in[10];
    const int*   mask = (const int*)d_in[11];
    float*       out  = (float*)d_out;

    __half *Xh, *Wqkvh, *W1h, *W2h, *QKVh, *Chp, *Hhp;
    float *bqkvp;
    int *mflagp;
    cudaGetSymbolAddress((void**)&Xh,     g_Xh);
    cudaGetSymbolAddress((void**)&Wqkvh,  g_Wqkvh);
    cudaGetSymbolAddress((void**)&W1h,    g_W1h);
    cudaGetSymbolAddress((void**)&W2h,    g_W2h);
    cudaGetSymbolAddress((void**)&QKVh,   g_QKVh);
    cudaGetSymbolAddress((void**)&Chp,    g_Ch);
    cudaGetSymbolAddress((void**)&Hhp,    g_Hh);
    cudaGetSymbolAddress((void**)&bqkvp,  g_bqkv);
    cudaGetSymbolAddress((void**)&mflagp, g_mflag);

    cudaFuncSetAttribute(attn_h,
                         cudaFuncAttributeMaxDynamicSharedMemorySize, ATTN_SMEM_BYTES);
    cudaFuncSetAttribute((const void*)gemm_h<0>,
                         cudaFuncAttributeMaxDynamicSharedMemorySize, HGEMM_SMEM);
    cudaFuncSetAttribute((const void*)gemm_h<1>,
                         cudaFuncAttributeMaxDynamicSharedMemorySize, HGEMM_SMEM);
    cudaFuncSetAttribute((const void*)gemm_h<2>,
                         cudaFuncAttributeMaxDynamicSharedMemorySize, HGEMM_SMEM);

    const dim3 blk(256);
    const int T = 256;

    // ---- prep ----
    HSegs P;
    P.src[0] = x;  P.dst[0] = Xh;
    P.src[1] = Wq; P.dst[1] = Wqkvh;
    P.src[2] = Wk; P.dst[2] = Wqkvh + (size_t)D_ * D_;
    P.src[3] = Wv; P.dst[3] = Wqkvh + (size_t)2 * D_ * D_;
    P.src[4] = W1; P.dst[4] = W1h;
    P.src[5] = W2; P.dst[5] = W2h;
    const int gr[6] = { M_ * D_ / 16, D_ * D_ / 16, D_ * D_ / 16, D_ * D_ / 16,
                        2 * D_ * D_ / 16, 2 * D_ * D_ / 16 };
    P.cum[0] = 0;
    for (int j = 0; j < 6; j++) P.cum[j + 1] = P.cum[j] + gr[j];
    round_half_all<<<(P.cum[6] + T - 1) / T, T>>>(P);
    concat_bias<<<(3 * D_ + T - 1) / T, T>>>(bq, bk, bv, bqkvp);
    mask_scan<<<B_ * (S_ / 128) * (S_ / 64), T>>>(mask, mflagp);

    // ---- fused QKV projection ----
    gemm_h<0><<<dim3(3 * D_ / 128, M_ / 128), blk, HGEMM_SMEM>>>(
        Xh, Wqkvh, bqkvp, (float*)nullptr, QKVh, M_, 3 * D_, D_);

    // ---- attention ----
    attn_h<<<dim3(S_ / QT_, B_ * H_), blk, ATTN_SMEM_BYTES>>>(QKVh, mask, mflagp, Chp);

    // ---- MLP ----
    gemm_h<1><<<dim3(2 * D_ / 128, M_ / 128), blk, HGEMM_SMEM>>>(
        Chp, W1h, b1, (float*)nullptr, Hhp, M_, 2 * D_, D_);
    gemm_h<2><<<dim3(D_ / 128, M_ / 128), blk, HGEMM_SMEM>>>(
        Hhp, W2h, b2, out, (__half*)nullptr, M_, D_, 2 * D_);
}

// round 12
// speedup vs baseline: 6.6497x; 1.1208x over previous
#include <cuda_runtime.h>
#include <cuda_fp16.h>
#include <stdint.h>

#define B_  4
#define S_  1024
#define D_  1024
#define H_  16
#define HD_ 64
#define M_  (B_ * S_)     // 4096

// ---------------------------------------------------------------------------
// Scratch (device globals)
// ---------------------------------------------------------------------------
__device__ __align__(16) __half g_Xh   [(size_t)M_ * D_];        // x, fp16
__device__ __align__(16) __half g_Wqkvh[(size_t)3 * D_ * D_];    // Wq|Wk|Wv
__device__ __align__(16) __half g_W1h  [(size_t)2 * D_ * D_];
__device__ __align__(16) __half g_W2h  [(size_t)2 * D_ * D_];
__device__ __align__(16) __half g_QKVh [(size_t)M_ * 3 * D_];    // Q,K permuted; V plain
__device__ __align__(16) __half g_Ch   [(size_t)M_ * D_];        // ctx fp16 (standard)
__device__ __align__(16) __half g_Hh   [(size_t)M_ * 2 * D_];    // hidden fp16 (standard)
__device__ __align__(16) float  g_bqkv [3 * D_];
__device__ int g_mflag[B_ * (S_ / 128) * (S_ / 64)];

// ---------------------------------------------------------------------------
__device__ __forceinline__ void mma_f16(float* c, const uint32_t* a, const uint32_t* b) {
    asm volatile(
        "mma.sync.aligned.m16n8k16.row.col.f32.f16.f16.f32 "
        "{%0,%1,%2,%3}, {%4,%5,%6,%7}, {%8,%9}, {%0,%1,%2,%3};\n"
        : "+f"(c[0]), "+f"(c[1]), "+f"(c[2]), "+f"(c[3])
        : "r"(a[0]), "r"(a[1]), "r"(a[2]), "r"(a[3]), "r"(b[0]), "r"(b[1]));
}

__device__ __forceinline__ void ldsm_x4(uint32_t& r0, uint32_t& r1,
                                        uint32_t& r2, uint32_t& r3, uint32_t addr) {
    asm volatile("ldmatrix.sync.aligned.m8n8.x4.shared.b16 {%0,%1,%2,%3}, [%4];"
                 : "=r"(r0), "=r"(r1), "=r"(r2), "=r"(r3) : "r"(addr));
}

__device__ __forceinline__ void ldsm_x4_t(uint32_t& r0, uint32_t& r1,
                                          uint32_t& r2, uint32_t& r3, uint32_t addr) {
    asm volatile("ldmatrix.sync.aligned.m8n8.x4.trans.shared.b16 {%0,%1,%2,%3}, [%4];"
                 : "=r"(r0), "=r"(r1), "=r"(r2), "=r"(r3) : "r"(addr));
}

__device__ __forceinline__ uint32_t smem_u32(const void* p) {
    uint32_t a;
    asm("{ .reg .u64 t; cvta.to.shared.u64 t, %1; cvt.u32.u64 %0, t; }"
        : "=r"(a) : "l"(p));
    return a;
}

__device__ __forceinline__ void cp_async16(uint32_t dst, const void* src) {
    asm volatile("cp.async.cg.shared.global [%0], [%1], 16;"
                 :: "r"(dst), "l"(src) : "memory");
}

__device__ __forceinline__ uint32_t packh2(float x, float y) {
    __half2 h = __floats2half2_rn(x, y);
    return *(uint32_t*)&h;
}

// logical (even) n -> permuted phys position within its 16-group (attention Q/K)
__device__ __forceinline__ int permn(int n0) {
    return (n0 & ~15) | (((n0 >> 1) & 3) << 2) | ((n0 & 8) >> 2);
}

// ---------------------------------------------------------------------------
// Prep: fp32 -> fp16 (standard layout), 16-element groups.
// ---------------------------------------------------------------------------
struct HSegs {
    const float* src[6];
    __half*      dst[6];
    int          cum[7];
};

__global__ void round_half_all(HSegs P) {
    const int i = blockIdx.x * blockDim.x + threadIdx.x;
    if (i >= P.cum[6]) return;
#pragma unroll
    for (int j = 0; j < 6; j++) {
        if (i < P.cum[j + 1]) {
            const int g = i - P.cum[j];
            const float4* s = (const float4*)P.src[j] + (size_t)g * 4;
            float l[16];
            *(float4*)&l[0]  = s[0];
            *(float4*)&l[4]  = s[1];
            *(float4*)&l[8]  = s[2];
            *(float4*)&l[12] = s[3];
            uint4 o0, o1;
            o0.x = packh2(l[0],  l[1]);  o0.y = packh2(l[2],  l[3]);
            o0.z = packh2(l[4],  l[5]);  o0.w = packh2(l[6],  l[7]);
            o1.x = packh2(l[8],  l[9]);  o1.y = packh2(l[10], l[11]);
            o1.z = packh2(l[12], l[13]); o1.w = packh2(l[14], l[15]);
            uint4* d = (uint4*)(P.dst[j] + (size_t)g * 16);
            d[0] = o0; d[1] = o1;
            return;
        }
    }
}

__global__ void concat_bias(const float* __restrict__ a, const float* __restrict__ b,
                            const float* __restrict__ c, float* __restrict__ dst) {
    const int i = blockIdx.x * blockDim.x + threadIdx.x;
    if (i < 3 * D_)
        dst[i] = (i < D_) ? a[i] : ((i < 2 * D_) ? b[i - D_] : c[i - 2 * D_]);
}

__global__ __launch_bounds__(256)
void mask_scan(const int* __restrict__ mask, int* __restrict__ flags) {
    const int fidx = blockIdx.x;
    const int kt = fidx & 15;
    const int qt = (fidx >> 4) & 7;
    const int b  = fidx >> 7;
    const int q0 = qt * 128;
    const int k0 = kt * 64;
    const int tid = threadIdx.x;

    int ok = 1;
#pragma unroll
    for (int i = 0; i < 8; i++) {
        const int idx = tid + 256 * i;
        const int row = idx >> 4;
        const int c4  = (idx & 15) * 4;
        const int4 v = *(const int4*)&mask[((size_t)(b * S_ + q0 + row)) * S_ + k0 + c4];
        if (v.x == 0 || v.y == 0 || v.z == 0 || v.w == 0) ok = 0;
    }
    const int all_ok = __syncthreads_and(ok);
    if (tid == 0) flags[fidx] = !all_ok;
}

// ---------------------------------------------------------------------------
// fp16 tensor-core GEMM: 128x128 tile, K-stage 64, 3-stage cp.async,
// XOR-swizzled smem (chunk ^ (row&7)) + ldmatrix fragment loads.
// MODE: 0 = QKV (fp16 out: Q prescale+perm, K perm, V plain),
//       1 = MLP1 (ReLU, standard fp16 out), 2 = MLP2 (fp32 out).
// ---------------------------------------------------------------------------
#define GROWB 128                      // 64 halves per row
#define GSTG_B (128 * GROWB)           // 16,384 per matrix per stage
#define GSTAGE_B (2 * GSTG_B)          // 32,768
#define GNST 3
#define HGEMM_SMEM (GNST * GSTAGE_B)   // 98,304

template <int MODE>
__global__ __launch_bounds__(256, 2)
void gemm_h(const __half* __restrict__ A, const __half* __restrict__ Bm,
            const float* __restrict__ bias, float* __restrict__ Cf,
            __half* __restrict__ Ch, int M, int N, int K)
{
    extern __shared__ __align__(16) char smc[];
    const uint32_t sb = smem_u32(smc);

    const int tid  = threadIdx.x;
    const int lane = tid & 31;
    const int wid  = tid >> 5;
    const int wm   = wid >> 2;
    const int wn   = wid & 3;
    const int grp  = lane >> 2;
    const int qid  = lane & 3;

    const int bm = blockIdx.y * 128;
    const int bn = blockIdx.x * 128;

    const __half* AgBase = A  + (size_t)bm * K;
    const __half* BgBase = Bm + (size_t)bn * K;

    auto issue_stage = [&](int stage, int buf) {
        const int k0 = stage * 64;
        const uint32_t sA = sb + (uint32_t)buf * GSTAGE_B;
        const uint32_t sB = sA + GSTG_B;
#pragma unroll
        for (int i = 0; i < 4; i++) {          // A: 1024 chunks of 16B
            const int ci  = tid + 256 * i;
            const int row = ci >> 3;
            const int c   = ci & 7;
            cp_async16(sA + (uint32_t)row * GROWB + (uint32_t)((c ^ (row & 7)) << 4),
                       AgBase + (size_t)row * K + k0 + c * 8);
        }
#pragma unroll
        for (int i = 0; i < 4; i++) {          // B: 1024 chunks
            const int ci  = tid + 256 * i;
            const int row = ci >> 3;
            const int c   = ci & 7;
            cp_async16(sB + (uint32_t)row * GROWB + (uint32_t)((c ^ (row & 7)) << 4),
                       BgBase + (size_t)row * K + k0 + c * 8);
        }
        asm volatile("cp.async.commit_group;" ::: "memory");
    };

    float acc[4][4][4];
#pragma unroll
    for (int i = 0; i < 4; i++)
#pragma unroll
        for (int j = 0; j < 4; j++)
#pragma unroll
            for (int r = 0; r < 4; r++) acc[i][j][r] = 0.f;

    const int KT = K / 64;

    issue_stage(0, 0);
    issue_stage(1, 1);

    // ldmatrix lane-address components (constant per thread)
    const int al8 = (lane & 7) + ((lane >> 3) & 1) * 8;   // row-within-16 for A
    const int ach = lane >> 4;                            // chunk parity for A
    const int bl8 = lane & 7;
    const int bg  = lane >> 3;                            // 0..3

    for (int kt = 0; kt < KT; kt++) {
        const int buf = kt % GNST;

        if (kt < KT - 1)
            asm volatile("cp.async.wait_group 1;" ::: "memory");
        else
            asm volatile("cp.async.wait_group 0;" ::: "memory");
        __syncthreads();

        if (kt + 2 < KT)
            issue_stage(kt + 2, (kt + 2) % GNST);

        const uint32_t sA = sb + (uint32_t)buf * GSTAGE_B;
        const uint32_t sB = sA + GSTG_B;

#pragma unroll
        for (int s = 0; s < 4; s++) {          // four k16 steps
            uint32_t a[4][4];
#pragma unroll
            for (int mf = 0; mf < 4; mf++) {
                const int arow = wm * 64 + mf * 16 + al8;
                const int c    = (s * 2 + ach) ^ (arow & 7);
                ldsm_x4(a[mf][0], a[mf][1], a[mf][2], a[mf][3],
                        sA + (uint32_t)arow * GROWB + (uint32_t)(c << 4));
            }
            uint32_t b[4][2];
#pragma unroll
            for (int nfp = 0; nfp < 2; nfp++) {
                const int brow = wn * 32 + nfp * 16 + (bg >> 1) * 8 + bl8;
                const int c    = (s * 2 + (bg & 1)) ^ (brow & 7);
                ldsm_x4(b[2 * nfp][0], b[2 * nfp][1], b[2 * nfp + 1][0], b[2 * nfp + 1][1],
                        sB + (uint32_t)brow * GROWB + (uint32_t)(c << 4));
            }
#pragma unroll
            for (int mf = 0; mf < 4; mf++)
#pragma unroll
                for (int nf = 0; nf < 4; nf++)
                    mma_f16(acc[mf][nf], a[mf], b[nf]);
        }
    }

    // ---- Epilogue ----
#pragma unroll
    for (int mf = 0; mf < 4; mf++) {
#pragma unroll
        for (int nf = 0; nf < 4; nf++) {
            const int m0 = bm + wm * 64 + mf * 16 + grp;
            const int n0 = bn + wn * 32 + nf * 8 + 2 * qid;
            const float bx = bias[n0], by = bias[n0 + 1];
            float2 v0, v1;
            v0.x = acc[mf][nf][0] + bx; v0.y = acc[mf][nf][1] + by;
            v1.x = acc[mf][nf][2] + bx; v1.y = acc[mf][nf][3] + by;

            if (MODE == 0) {
                if (n0 < D_) {
                    v0.x *= 0.125f; v0.y *= 0.125f;
                    v1.x *= 0.125f; v1.y *= 0.125f;
                }
                const int pn = (n0 < 2 * D_) ? permn(n0) : n0;
                *(uint32_t*)&Ch[(size_t)m0 * N + pn]       = packh2(v0.x, v0.y);
                *(uint32_t*)&Ch[(size_t)(m0 + 8) * N + pn] = packh2(v1.x, v1.y);
            } else if (MODE == 1) {
                v0.x = fmaxf(v0.x, 0.f); v0.y = fmaxf(v0.y, 0.f);
                v1.x = fmaxf(v1.x, 0.f); v1.y = fmaxf(v1.y, 0.f);
                *(uint32_t*)&Ch[(size_t)m0 * N + n0]       = packh2(v0.x, v0.y);
                *(uint32_t*)&Ch[(size_t)(m0 + 8) * N + n0] = packh2(v1.x, v1.y);
            } else {
                *(float2*)&Cf[(size_t)m0 * N + n0]       = v0;
                *(float2*)&Cf[(size_t)(m0 + 8) * N + n0] = v1;
            }
        }
    }
}

// ---------------------------------------------------------------------------
// fp16 tensor-core flash attention + per-tile mask dirty flags (R11),
// ctx finalize now writes STANDARD fp16 layout (for ldmatrix MLP1).
// ---------------------------------------------------------------------------
#define QT_ 128
#define QSTRB 160
#define KSTRB 160
#define VSTRB 144
#define QS_BYTES   (QT_ * QSTRB)
#define KSTG_BYTES (64 * KSTRB)
#define VSTG_BYTES (64 * VSTRB)
#define ATTN_SMEM_BYTES (QS_BYTES + 2 * KSTG_BYTES + 2 * VSTG_BYTES)  // 59,392

__global__ __launch_bounds__(256, 2)
void attn_h(const __half* __restrict__ QKV, const int* __restrict__ mask,
            const int* __restrict__ mflag, __half* __restrict__ O)
{
    extern __shared__ __align__(16) char smb[];
    const uint32_t sb  = smem_u32(smb);
    const uint32_t sQ  = sb;
    const uint32_t sK  = sb + QS_BYTES;
    const uint32_t sV  = sK + 2 * KSTG_BYTES;
    const char* Qsp = smb;
    const char* Ksp = smb + QS_BYTES;

    const int tid  = threadIdx.x;
    const int lane = tid & 31;
    const int wid  = tid >> 5;
    const int grp  = lane >> 2;
    const int qid  = lane & 3;

    const int qt = blockIdx.x;
    const int bh = blockIdx.y;
    const int b  = bh >> 4;
    const int h  = bh & 15;
    const int q0 = qt * QT_;

    const int LDQ = 3 * D_;
    const __half* Qb = QKV + (size_t)b * S_ * LDQ + (size_t)h * HD_;
    const __half* Kb = Qb + D_;
    const __half* Vb = Qb + 2 * D_;
    const int* mfbase = mflag + (b * (S_ / QT_) + qt) * (S_ / 64);

    auto issue_kv = [&](int kt, int buf) {
        const int k0g = kt * 64;
#pragma unroll
        for (int i = 0; i < 2; i++) {
            const int idx = tid + 256 * i;
            const int row = idx >> 3;
            const int ch  = idx & 7;
            cp_async16(sK + (uint32_t)buf * KSTG_BYTES + (uint32_t)row * KSTRB + ch * 16,
                       Kb + (size_t)(k0g + row) * LDQ + ch * 8);
            cp_async16(sV + (uint32_t)buf * VSTG_BYTES + (uint32_t)row * VSTRB + ch * 16,
                       Vb + (size_t)(k0g + row) * LDQ + ch * 8);
        }
        asm volatile("cp.async.commit_group;" ::: "memory");
    };

    issue_kv(0, 0);

#pragma unroll
    for (int i = 0; i < 4; i++) {
        const int idx = tid + 256 * i;
        const int row = idx >> 3;
        const int ch  = idx & 7;
        cp_async16(sQ + (uint32_t)row * QSTRB + ch * 16,
                   Qb + (size_t)(q0 + row) * LDQ + ch * 8);
    }
    asm volatile("cp.async.commit_group;" ::: "memory");

    const int qrow0 = wid * 16 + grp;
    const int* mrow0 = mask + (size_t)(b * S_ + q0 + qrow0) * S_;
    const int* mrow1 = mrow0 + 8 * S_;

    float mi0 = -1e30f, mi1 = -1e30f, li0 = 0.f, li1 = 0.f;
    float o[8][4];
#pragma unroll
    for (int nf = 0; nf < 8; nf++)
#pragma unroll
        for (int r = 0; r < 4; r++) o[nf][r] = 0.f;

    for (int kt = 0; kt < S_ / 64; kt++) {
        const int buf = kt & 1;
        const int k0  = kt * 64;
        const bool dirty = mfbase[kt] != 0;

        asm volatile("cp.async.wait_group 0;" ::: "memory");
        __syncthreads();

        if (kt + 1 < S_ / 64)
            issue_kv(kt + 1, buf ^ 1);

        const char* Kb2 = Ksp + (size_t)buf * KSTG_BYTES;
        const uint32_t Vb2 = sV + (uint32_t)buf * VSTG_BYTES;

        // ---- QK^T (Q,K permuted fp16: LDS.64 fragments) ----
        float c[8][4];
#pragma unroll
        for (int nf = 0; nf < 8; nf++)
#pragma unroll
            for (int r = 0; r < 4; r++) c[nf][r] = 0.f;

#pragma unroll
        for (int s = 0; s < 4; s++) {
            const uint2 lo = *(const uint2*)(Qsp + qrow0 * QSTRB + s * 32 + qid * 8);
            const uint2 hi = *(const uint2*)(Qsp + (qrow0 + 8) * QSTRB + s * 32 + qid * 8);
            uint32_t a[4] = { lo.x, hi.x, lo.y, hi.y };
#pragma unroll
            for (int nf = 0; nf < 8; nf++) {
                const uint2 bv = *(const uint2*)(Kb2 + (nf * 8 + grp) * KSTRB + s * 32 + qid * 8);
                uint32_t bb[2] = { bv.x, bv.y };
                mma_f16(c[nf], a, bb);
            }
        }

        if (dirty) {
#pragma unroll
            for (int nf = 0; nf < 8; nf++) {
                const int kc = k0 + nf * 8 + 2 * qid;
                const int2 m0 = *(const int2*)&mrow0[kc];
                const int2 m1 = *(const int2*)&mrow1[kc];
                if (m0.x == 0) c[nf][0] = -1e8f;
                if (m0.y == 0) c[nf][1] = -1e8f;
                if (m1.x == 0) c[nf][2] = -1e8f;
                if (m1.y == 0) c[nf][3] = -1e8f;
            }
        }

        float mx0 = -1e30f, mx1 = -1e30f;
#pragma unroll
        for (int nf = 0; nf < 8; nf++) {
            mx0 = fmaxf(mx0, fmaxf(c[nf][0], c[nf][1]));
            mx1 = fmaxf(mx1, fmaxf(c[nf][2], c[nf][3]));
        }
        mx0 = fmaxf(mx0, __shfl_xor_sync(0xffffffffu, mx0, 1));
        mx0 = fmaxf(mx0, __shfl_xor_sync(0xffffffffu, mx0, 2));
        mx1 = fmaxf(mx1, __shfl_xor_sync(0xffffffffu, mx1, 1));
        mx1 = fmaxf(mx1, __shfl_xor_sync(0xffffffffu, mx1, 2));

        const float mn0 = fmaxf(mi0, mx0);
        const float mn1 = fmaxf(mi1, mx1);
        const float al0 = __expf(mi0 - mn0);
        const float al1 = __expf(mi1 - mn1);

        float sum0 = 0.f, sum1 = 0.f;
#pragma unroll
        for (int nf = 0; nf < 8; nf++) {
            float e;
            e = __expf(c[nf][0] - mn0); sum0 += e; c[nf][0] = e;
            e = __expf(c[nf][1] - mn0); sum0 += e; c[nf][1] = e;
            e = __expf(c[nf][2] - mn1); sum1 += e; c[nf][2] = e;
            e = __expf(c[nf][3] - mn1); sum1 += e; c[nf][3] = e;
        }
        sum0 += __shfl_xor_sync(0xffffffffu, sum0, 1);
        sum0 += __shfl_xor_sync(0xffffffffu, sum0, 2);
        sum1 += __shfl_xor_sync(0xffffffffu, sum1, 1);
        sum1 += __shfl_xor_sync(0xffffffffu, sum1, 2);

        li0 = li0 * al0 + sum0;  mi0 = mn0;
        li1 = li1 * al1 + sum1;  mi1 = mn1;

#pragma unroll
        for (int nf = 0; nf < 8; nf++) {
            o[nf][0] *= al0; o[nf][1] *= al0;
            o[nf][2] *= al1; o[nf][3] *= al1;
        }

        // ---- PV: V via ldmatrix.trans ----
        const int lmi = lane >> 3;
        const int lmr = lane & 7;
#pragma unroll
        for (int s = 0; s < 4; s++) {
            uint32_t a[4];
            a[0] = packh2(c[2 * s][0],     c[2 * s][1]);
            a[1] = packh2(c[2 * s][2],     c[2 * s][3]);
            a[2] = packh2(c[2 * s + 1][0], c[2 * s + 1][1]);
            a[3] = packh2(c[2 * s + 1][2], c[2 * s + 1][3]);
#pragma unroll
            for (int nfp = 0; nfp < 4; nfp++) {
                const int vrow = 16 * s + ((lmi & 1) << 3) + lmr;
                const int vcol = 16 * nfp + ((lmi >> 1) << 3);
                uint32_t b0, b1, b2, b3;
                ldsm_x4_t(b0, b1, b2, b3,
                          Vb2 + (uint32_t)vrow * VSTRB + (uint32_t)vcol * 2);
                { uint32_t bb[2] = { b0, b1 }; mma_f16(o[2 * nfp],     a, bb); }
                { uint32_t bb[2] = { b2, b3 }; mma_f16(o[2 * nfp + 1], a, bb); }
            }
        }
    }

    // ---- finalize: ctx standard fp16 ----
    const float inv0 = 1.0f / li0;
    const float inv1 = 1.0f / li1;
    __half* row0g = O + (size_t)(b * S_ + q0 + qrow0) * D_ + (size_t)h * HD_;
    __half* row1g = row0g + (size_t)8 * D_;
#pragma unroll
    for (int nf = 0; nf < 8; nf++) {
        const int d0 = nf * 8 + 2 * qid;
        *(uint32_t*)(row0g + d0) = packh2(o[nf][0] * inv0, o[nf][1] * inv0);
        *(uint32_t*)(row1g + d0) = packh2(o[nf][2] * inv1, o[nf][3] * inv1);
    }
}

// ---------------------------------------------------------------------------
// Launch.  Inputs: x, Wq, bq, Wk, bk, Wv, bv, W1, b1, W2, b2, mask
// ---------------------------------------------------------------------------
extern "C" void kernel_launch(void* const* d_in, const int* in_sizes, int n_in,
                              void* d_out, int out_size)
{
    const float* x    = (const float*)d_in[0];
    const float* Wq   = (const float*)d_in[1];
    const float* bq   = (const float*)d_in[2];
    const float* Wk   = (const float*)d_in[3];
    const float* bk   = (const float*)d_in[4];
    const float* Wv   = (const float*)d_in[5];
    const float* bv   = (const float*)d_in[6];
    const float* W1   = (const float*)d_in[7];
    const float* b1   = (const float*)d_in[8];
    const float* W2   = (const float*)d_in[9];
    const float* b2   = (const float*)d_in[10];
    const int*   mask = (const int*)d_in[11];
    float*       out  = (float*)d_out;

    __half *Xh, *Wqkvh, *W1h, *W2h, *QKVh, *Chp, *Hhp;
    float *bqkvp;
    int *mflagp;
    cudaGetSymbolAddress((void**)&Xh,     g_Xh);
    cudaGetSymbolAddress((void**)&Wqkvh,  g_Wqkvh);
    cudaGetSymbolAddress((void**)&W1h,    g_W1h);
    cudaGetSymbolAddress((void**)&W2h,    g_W2h);
    cudaGetSymbolAddress((void**)&QKVh,   g_QKVh);
    cudaGetSymbolAddress((void**)&Chp,    g_Ch);
    cudaGetSymbolAddress((void**)&Hhp,    g_Hh);
    cudaGetSymbolAddress((void**)&bqkvp,  g_bqkv);
    cudaGetSymbolAddress((void**)&mflagp, g_mflag);

    cudaFuncSetAttribute(attn_h,
                         cudaFuncAttributeMaxDynamicSharedMemorySize, ATTN_SMEM_BYTES);
    cudaFuncSetAttribute((const void*)gemm_h<0>,
                         cudaFuncAttributeMaxDynamicSharedMemorySize, HGEMM_SMEM);
    cudaFuncSetAttribute((const void*)gemm_h<1>,
                         cudaFuncAttributeMaxDynamicSharedMemorySize, HGEMM_SMEM);
    cudaFuncSetAttribute((const void*)gemm_h<2>,
                         cudaFuncAttributeMaxDynamicSharedMemorySize, HGEMM_SMEM);

    const dim3 blk(256);
    const int T = 256;

    // ---- prep ----
    HSegs P;
    P.src[0] = x;  P.dst[0] = Xh;
    P.src[1] = Wq; P.dst[1] = Wqkvh;
    P.src[2] = Wk; P.dst[2] = Wqkvh + (size_t)D_ * D_;
    P.src[3] = Wv; P.dst[3] = Wqkvh + (size_t)2 * D_ * D_;
    P.src[4] = W1; P.dst[4] = W1h;
    P.src[5] = W2; P.dst[5] = W2h;
    const int gr[6] = { M_ * D_ / 16, D_ * D_ / 16, D_ * D_ / 16, D_ * D_ / 16,
                        2 * D_ * D_ / 16, 2 * D_ * D_ / 16 };
    P.cum[0] = 0;
    for (int j = 0; j < 6; j++) P.cum[j + 1] = P.cum[j] + gr[j];
    round_half_all<<<(P.cum[6] + T - 1) / T, T>>>(P);
    concat_bias<<<(3 * D_ + T - 1) / T, T>>>(bq, bk, bv, bqkvp);
    mask_scan<<<B_ * (S_ / 128) * (S_ / 64), T>>>(mask, mflagp);

    // ---- fused QKV projection ----
    gemm_h<0><<<dim3(3 * D_ / 128, M_ / 128), blk, HGEMM_SMEM>>>(
        Xh, Wqkvh, bqkvp, (float*)nullptr, QKVh, M_, 3 * D_, D_);

    // ---- attention ----
    attn_h<<<dim3(S_ / QT_, B_ * H_), blk, ATTN_SMEM_BYTES>>>(QKVh, mask, mflagp, Chp);

    // ---- MLP ----
    gemm_h<1><<<dim3(2 * D_ / 128, M_ / 128), blk, HGEMM_SMEM>>>(
        Chp, W1h, b1, (float*)nullptr, Hhp, M_, 2 * D_, D_);
    gemm_h<2><<<dim3(D_ / 128, M_ / 128), blk, HGEMM_SMEM>>>(
        Hhp, W2h, b2, out, (__half*)nullptr, M_, D_, 2 * D_);
}